// round 10
// baseline (speedup 1.0000x reference)
#include <cuda_runtime.h>
#include <cuda_fp16.h>
#include <cstdint>

#define DEV_INLINE __device__ __forceinline__

// ---------------- problem constants (fixed shapes) ----------------
constexpr int Bc = 4, Tc = 2048, Dc = 4096, OUTc = 4096, RANKc = 128, SELECTc = 128, GROUPc = 16;
constexpr int MTOK = Bc * Tc;         // 8192 token rows
constexpr int SPARSE_T = 204;         // int(2048 * (1 - 0.9))
constexpr float SCALE_CAP = 448.0f * 6.0f;
constexpr int KFUSE = Dc + RANKc;     // 4224

// ---------------- scratch (device globals) ----------------
__device__ __half  g_Xh [(size_t)MTOK * Dc];
__device__ __half  g_Xl [(size_t)MTOK * Dc];
__device__ __half  g_LRh[(size_t)MTOK * Dc];
__device__ __half  g_LRl[(size_t)MTOK * Dc];
__device__ __half  g_Whh[(size_t)OUTc * Dc];
__device__ __half  g_Wll[(size_t)OUTc * Dc];
__device__ __half  g_vsh[(size_t)RANKc * Dc];   // vs^T [r][d]
__device__ __half  g_vsl[(size_t)RANKc * Dc];
__device__ __half  g_uth[(size_t)OUTc * RANKc]; // u_t^T [o][r]
__device__ __half  g_utl[(size_t)OUTc * RANKc];
__device__ __half  g_tmph[(size_t)MTOK * RANKc];
__device__ __half  g_tmpl[(size_t)MTOK * RANKc];
__device__ float   g_tmp4[4][(size_t)MTOK * RANKc]; // K-split partials
__device__ unsigned g_maxbits[2];

DEV_INLINE void split2(float v, __half& h, __half& l) {
    __half hh = __float2half(v);
    h = hh;
    l = __float2half(v - __half2float(hh));
}

// ---------------- fused operand conversion ----------------
__global__ void __launch_bounds__(256) convert_all_kernel(const float* __restrict__ W,
                                                          const float* __restrict__ vs,
                                                          const float* __restrict__ u_t) {
    if (blockIdx.x == 0 && threadIdx.x < 2) g_maxbits[threadIdx.x] = 0u;
    if (blockIdx.x < 2048) {
        const size_t base = (size_t)blockIdx.x * (OUTc * Dc / 2048);
        const size_t cnt = OUTc * Dc / 2048; // 8192 per block
        for (size_t k = threadIdx.x * 4; k < cnt; k += 1024) {
            float4 v4 = *reinterpret_cast<const float4*>(W + base + k);
            __half h0, l0, h1, l1, h2, l2, h3, l3;
            split2(v4.x, h0, l0); split2(v4.y, h1, l1);
            split2(v4.z, h2, l2); split2(v4.w, h3, l3);
            __half2 hh01 = __halves2half2(h0, h1), hh23 = __halves2half2(h2, h3);
            __half2 ll01 = __halves2half2(l0, l1), ll23 = __halves2half2(l2, l3);
            uint2 uh, ul;
            uh.x = *reinterpret_cast<unsigned*>(&hh01); uh.y = *reinterpret_cast<unsigned*>(&hh23);
            ul.x = *reinterpret_cast<unsigned*>(&ll01); ul.y = *reinterpret_cast<unsigned*>(&ll23);
            *reinterpret_cast<uint2*>(g_Whh + base + k) = uh;
            *reinterpret_cast<uint2*>(g_Wll + base + k) = ul;
        }
    } else {
        const int b = blockIdx.x - 2048;
        const int n = Dc * RANKc;
        const int stride = 512 * 256;
        for (int i = b * 256 + threadIdx.x; i < n; i += stride) {
            int d = i / RANKc, r = i - d * RANKc;
            __half h, l; split2(vs[i], h, l);
            g_vsh[(size_t)r * Dc + d] = h;
            g_vsl[(size_t)r * Dc + d] = l;
        }
        for (int i = b * 256 + threadIdx.x; i < n; i += stride) {
            int r = i / OUTc, o = i - r * OUTc;
            __half h, l; split2(u_t[i], h, l);
            g_uth[(size_t)o * RANKc + r] = h;
            g_utl[(size_t)o * RANKc + r] = l;
        }
    }
}

__global__ void reduce_max_kernel(const float* __restrict__ x,
                                  const float* __restrict__ scale_vec,
                                  const float* __restrict__ threshold) {
    const float thr = threshold[0];
    float mpre = 0.f, mdec = 0.f;
    const size_t n4 = (size_t)MTOK * Dc / 4;
    for (size_t i4 = (size_t)blockIdx.x * blockDim.x + threadIdx.x; i4 < n4;
         i4 += (size_t)gridDim.x * blockDim.x) {
        size_t i = i4 * 4;
        int d = (int)(i & (Dc - 1));
        int t = (int)((i >> 12) & (Tc - 1));
        float4 v = *reinterpret_cast<const float4*>(x + i);
        if (t < SPARSE_T) {
            mpre = fmaxf(mpre, fmaxf(fmaxf(fabsf(v.x), fabsf(v.y)), fmaxf(fabsf(v.z), fabsf(v.w))));
        } else {
            float4 sv = *reinterpret_cast<const float4*>(scale_vec + d);
            if (fabsf(v.x * sv.x) > thr) mdec = fmaxf(mdec, fabsf(v.x));
            if (fabsf(v.y * sv.y) > thr) mdec = fmaxf(mdec, fabsf(v.y));
            if (fabsf(v.z * sv.z) > thr) mdec = fmaxf(mdec, fabsf(v.z));
            if (fabsf(v.w * sv.w) > thr) mdec = fmaxf(mdec, fabsf(v.w));
        }
    }
#pragma unroll
    for (int o = 16; o; o >>= 1) {
        mpre = fmaxf(mpre, __shfl_xor_sync(0xffffffffu, mpre, o));
        mdec = fmaxf(mdec, __shfl_xor_sync(0xffffffffu, mdec, o));
    }
    __shared__ float spre[8], sdec[8];
    int w = threadIdx.x >> 5;
    if ((threadIdx.x & 31) == 0) { spre[w] = mpre; sdec[w] = mdec; }
    __syncthreads();
    if (threadIdx.x == 0) {
        float a = spre[0], b = sdec[0];
        for (int i = 1; i < (int)(blockDim.x >> 5); i++) {
            a = fmaxf(a, spre[i]); b = fmaxf(b, sdec[i]);
        }
        atomicMax(&g_maxbits[0], __float_as_uint(a));
        atomicMax(&g_maxbits[1], __float_as_uint(b));
    }
}

DEV_INLINE float fp4_mag(float a) {
    return a > 2.5f ? (a > 3.5f ? (a > 5.0f ? 6.0f : 4.0f) : 3.0f)
                    : (a > 1.25f ? (a > 1.75f ? 2.0f : 1.5f)
                                 : (a > 0.75f ? 1.0f : (a > 0.25f ? 0.5f : 0.0f)));
}

__global__ void __launch_bounds__(256) quantize_kernel(const float* __restrict__ x,
                                                       const float* __restrict__ scale_vec,
                                                       const float* __restrict__ threshold,
                                                       const int* __restrict__ rix) {
    __shared__ float  sx[Dc];
    __shared__ int    sri[Dc];

    const int tok = blockIdx.x;
    const int t = tok & (Tc - 1);
    const bool decode = (t >= SPARSE_T);
    const float thr = threshold[0];
    const float s = fmaxf(__uint_as_float(g_maxbits[decode ? 1 : 0]) / SCALE_CAP, 1e-12f);
    const float inv_s = 1.0f / s;
    const float* xrow = x + (size_t)tok * Dc;
    const int tid = threadIdx.x;

    __half* lrh = g_LRh + (size_t)tok * Dc;
    __half* lrl = g_LRl + (size_t)tok * Dc;

#pragma unroll
    for (int it = 0; it < 4; it++) {
        int i = it * 1024 + tid * 4;
        float4 v = *reinterpret_cast<const float4*>(xrow + i);
        *reinterpret_cast<int4*>(sri + i) = *reinterpret_cast<const int4*>(rix + i);
        float4 masked, lr;
        if (decode) {
            float4 sv = *reinterpret_cast<const float4*>(scale_vec + i);
            bool m0 = fabsf(v.x * sv.x) > thr, m1 = fabsf(v.y * sv.y) > thr;
            bool m2 = fabsf(v.z * sv.z) > thr, m3 = fabsf(v.w * sv.w) > thr;
            masked = make_float4(m0 ? v.x : 0.f, m1 ? v.y : 0.f, m2 ? v.z : 0.f, m3 ? v.w : 0.f);
            lr     = make_float4(m0 ? 0.f : v.x, m1 ? 0.f : v.y, m2 ? 0.f : v.z, m3 ? 0.f : v.w);
        } else {
            masked = v; lr = make_float4(0.f, 0.f, 0.f, 0.f);
        }
        *reinterpret_cast<float4*>(sx + i) = masked;
        __half h0, l0, h1, l1, h2, l2, h3, l3;
        split2(lr.x, h0, l0); split2(lr.y, h1, l1);
        split2(lr.z, h2, l2); split2(lr.w, h3, l3);
        __half2 hh01 = __halves2half2(h0, h1), hh23 = __halves2half2(h2, h3);
        __half2 ll01 = __halves2half2(l0, l1), ll23 = __halves2half2(l2, l3);
        uint2 uh, ul;
        uh.x = *reinterpret_cast<unsigned*>(&hh01); uh.y = *reinterpret_cast<unsigned*>(&hh23);
        ul.x = *reinterpret_cast<unsigned*>(&ll01); ul.y = *reinterpret_cast<unsigned*>(&ll23);
        *reinterpret_cast<uint2*>(lrh + i) = uh;
        *reinterpret_cast<uint2*>(lrl + i) = ul;
    }
    __syncthreads();

    if (tid < 8) {
#pragma unroll
        for (int k = 0; k < 16; k++) {
            int ri = sri[tid * 16 + k];
            float xr = sx[ri] * inv_s;
            sx[ri] = xr * s;
        }
    } else {
        const int j0 = SELECTc + (tid - 8) * GROUPc;
        float gmax = 0.f;
#pragma unroll
        for (int k = 0; k < GROUPc; k++) {
            float v = sx[sri[j0 + k]] * inv_s;
            gmax = fmaxf(gmax, fabsf(v));
        }
        float gs, inv_gs;
        if (gmax > 0.f) { gs = gmax / 6.0f; inv_gs = 6.0f / gmax; }
        else            { gs = 1.0f;       inv_gs = 1.0f; }
#pragma unroll
        for (int k = 0; k < GROUPc; k++) {
            int ri = sri[j0 + k];
            float v = sx[ri] * inv_s;
            float r = v * inv_gs;
            float q = fp4_mag(fabsf(r));
            q = (r < 0.f) ? -q : q;
            sx[ri] = (q * gs) * s;
        }
    }
    __syncthreads();

    __half* xh = g_Xh + (size_t)tok * Dc;
    __half* xl = g_Xl + (size_t)tok * Dc;
#pragma unroll
    for (int it = 0; it < 4; it++) {
        int i = it * 1024 + tid * 4;
        float4 v = *reinterpret_cast<const float4*>(sx + i);
        __half h0, l0, h1, l1, h2, l2, h3, l3;
        split2(v.x, h0, l0); split2(v.y, h1, l1);
        split2(v.z, h2, l2); split2(v.w, h3, l3);
        __half2 hh01 = __halves2half2(h0, h1), hh23 = __halves2half2(h2, h3);
        __half2 ll01 = __halves2half2(l0, l1), ll23 = __halves2half2(l2, l3);
        uint2 uh, ul;
        uh.x = *reinterpret_cast<unsigned*>(&hh01); uh.y = *reinterpret_cast<unsigned*>(&hh23);
        ul.x = *reinterpret_cast<unsigned*>(&ll01); ul.y = *reinterpret_cast<unsigned*>(&ll23);
        *reinterpret_cast<uint2*>(xh + i) = uh;
        *reinterpret_cast<uint2*>(xl + i) = ul;
    }
}

__global__ void sum_split_kernel() {
    int i = blockIdx.x * blockDim.x + threadIdx.x;
    if (i < MTOK * RANKc) {
        float s = g_tmp4[0][i] + g_tmp4[1][i] + g_tmp4[2][i] + g_tmp4[3][i];
        __half h, l; split2(s, h, l);
        g_tmph[i] = h; g_tmpl[i] = l;
    }
}

// ---------------- PTX helpers ----------------
DEV_INLINE unsigned smem_u32(const void* p) { return (unsigned)__cvta_generic_to_shared(p); }

DEV_INLINE void cp_async16(unsigned dst, const void* src) {
    asm volatile("cp.async.cg.shared.global [%0], [%1], 16;\n" :: "r"(dst), "l"(src));
}
DEV_INLINE void cp_commit() { asm volatile("cp.async.commit_group;\n"); }
template <int N> DEV_INLINE void cp_wait() { asm volatile("cp.async.wait_group %0;\n" :: "n"(N)); }

DEV_INLINE void ldmatrix_x4(unsigned& r0, unsigned& r1, unsigned& r2, unsigned& r3, unsigned addr) {
    asm volatile("ldmatrix.sync.aligned.m8n8.x4.shared.b16 {%0,%1,%2,%3}, [%4];\n"
                 : "=r"(r0), "=r"(r1), "=r"(r2), "=r"(r3) : "r"(addr));
}
DEV_INLINE void mma16816(float& d0, float& d1, float& d2, float& d3,
                         unsigned a0, unsigned a1, unsigned a2, unsigned a3,
                         unsigned b0, unsigned b1) {
    asm volatile("mma.sync.aligned.m16n8k16.row.col.f32.f16.f16.f32 "
                 "{%0,%1,%2,%3}, {%4,%5,%6,%7}, {%8,%9}, {%0,%1,%2,%3};\n"
                 : "+f"(d0), "+f"(d1), "+f"(d2), "+f"(d3)
                 : "r"(a0), "r"(a1), "r"(a2), "r"(a3), "r"(b0), "r"(b1));
}

// ================= fused main GEMM: 512 threads, 128x256x32 tile =================
// R8's proven 3-stage / distance-2 / single-barrier pipeline, BN widened to 256.
// stage layout (uint4): Ah[512] Al[512] Bh[1024] Bl[1024] = 3072/stage; 3 stages = 144 KB.
constexpr int MAIN_KT = KFUSE / 32;           // 132
constexpr int MAIN_SMEM = 3 * 3072 * 16;      // 144 KB

__global__ void __launch_bounds__(512, 1)
gemm_main_kernel(const __half* __restrict__ Ah, const __half* __restrict__ Al,
                 const __half* __restrict__ Bh, const __half* __restrict__ Bl,
                 const __half* __restrict__ Eah, const __half* __restrict__ Eal,
                 const __half* __restrict__ Ebh, const __half* __restrict__ Ebl,
                 float* __restrict__ C, const float* __restrict__ bias) {
    extern __shared__ uint4 S[];
    const int tid = threadIdx.x;

    // raster: 1024 CTAs = 8 groups x (16 mt x 8 nt); group working set ~67MB < L2
    const int bid = blockIdx.x;
    const int gid = bid >> 7, wit = bid & 127;
    const int mt = (gid >> 1) * 16 + (wit & 15);
    const int nt = (gid & 1) * 8 + (wit >> 4);
    const int rowA0 = mt * 128;
    const int rowB0 = nt * 256;

    auto load_tile = [&](int stage, int kt) {
        const int so = stage * 3072;
        const bool mainseg = (kt < Dc / 32);
        const int k0 = mainseg ? kt * 32 : (kt - Dc / 32) * 32;
        // A: 128 rows x 4 chunks = 512
#pragma unroll
        for (int i = tid; i < 512; i += 512) {
            int r = i >> 2, c = i & 3;
            int d = so + (r << 2) + (c ^ ((r >> 1) & 3));
            if (mainseg) {
                size_t src = (size_t)(rowA0 + r) * Dc + k0 + c * 8;
                cp_async16(smem_u32(&S[d]), Ah + src);
                cp_async16(smem_u32(&S[d + 512]), Al + src);
            } else {
                size_t src = (size_t)(rowA0 + r) * RANKc + k0 + c * 8;
                cp_async16(smem_u32(&S[d]), Eah + src);
                cp_async16(smem_u32(&S[d + 512]), Eal + src);
            }
        }
        // B: 256 rows x 4 chunks = 1024
#pragma unroll
        for (int i = tid; i < 1024; i += 512) {
            int r = i >> 2, c = i & 3;
            int d = so + 1024 + (r << 2) + (c ^ ((r >> 1) & 3));
            if (mainseg) {
                size_t src = (size_t)(rowB0 + r) * Dc + k0 + c * 8;
                cp_async16(smem_u32(&S[d]), Bh + src);
                cp_async16(smem_u32(&S[d + 1024]), Bl + src);
            } else {
                size_t src = (size_t)(rowB0 + r) * RANKc + k0 + c * 8;
                cp_async16(smem_u32(&S[d]), Ebh + src);
                cp_async16(smem_u32(&S[d + 1024]), Ebl + src);
            }
        }
        cp_commit();
    };

    const int warp = tid >> 5, lane = tid & 31;
    const int wm = warp & 1;    // 2 warp-rows of 64
    const int wn = warp >> 1;   // 8 warp-cols of 32

    float acc[4][4][4];
#pragma unroll
    for (int i = 0; i < 4; i++)
#pragma unroll
        for (int j = 0; j < 4; j++)
#pragma unroll
            for (int k = 0; k < 4; k++) acc[i][j][k] = 0.f;

    load_tile(0, 0);
    load_tile(1, 1);

    int cstage = 0;
    for (int kt = 0; kt < MAIN_KT; kt++) {
        if (kt >= MAIN_KT - 1) cp_wait<0>(); else cp_wait<1>();
        __syncthreads();
        if (kt + 2 < MAIN_KT) {
            int lstage = cstage == 0 ? 2 : cstage - 1;
            load_tile(lstage, kt + 2);
        }
        const int so = cstage * 3072;
#pragma unroll
        for (int ks = 0; ks < 2; ks++) {
            unsigned bh[4][2], bl[4][2];
#pragma unroll
            for (int nb = 0; nb < 2; nb++) {
                int n = wn * 32 + nb * 16 + (lane & 7) + ((lane >> 4) << 3);
                int kc = ks * 2 + ((lane >> 3) & 1);
                int idx = so + 1024 + (n << 2) + (kc ^ ((n >> 1) & 3));
                unsigned r0, r1, r2, r3;
                ldmatrix_x4(r0, r1, r2, r3, smem_u32(&S[idx]));
                bh[nb * 2][0] = r0;     bh[nb * 2][1] = r1;
                bh[nb * 2 + 1][0] = r2; bh[nb * 2 + 1][1] = r3;
                ldmatrix_x4(r0, r1, r2, r3, smem_u32(&S[idx + 1024]));
                bl[nb * 2][0] = r0;     bl[nb * 2][1] = r1;
                bl[nb * 2 + 1][0] = r2; bl[nb * 2 + 1][1] = r3;
            }
#pragma unroll
            for (int mp = 0; mp < 2; mp++) {
                unsigned ah[2][4], al[2][4];
#pragma unroll
                for (int m2 = 0; m2 < 2; m2++) {
                    int mi = mp * 2 + m2;
                    int m = wm * 64 + mi * 16 + (lane & 15);
                    int kc = ks * 2 + (lane >> 4);
                    int idx = so + (m << 2) + (kc ^ ((m >> 1) & 3));
                    ldmatrix_x4(ah[m2][0], ah[m2][1], ah[m2][2], ah[m2][3], smem_u32(&S[idx]));
                    ldmatrix_x4(al[m2][0], al[m2][1], al[m2][2], al[m2][3], smem_u32(&S[idx + 512]));
                }
#pragma unroll
                for (int m2 = 0; m2 < 2; m2++)
#pragma unroll
                    for (int ni = 0; ni < 4; ni++) {
                        float* d = acc[mp * 2 + m2][ni];
                        mma16816(d[0], d[1], d[2], d[3],
                                 ah[m2][0], ah[m2][1], ah[m2][2], ah[m2][3], bh[ni][0], bh[ni][1]);
                        mma16816(d[0], d[1], d[2], d[3],
                                 al[m2][0], al[m2][1], al[m2][2], al[m2][3], bh[ni][0], bh[ni][1]);
                        mma16816(d[0], d[1], d[2], d[3],
                                 ah[m2][0], ah[m2][1], ah[m2][2], ah[m2][3], bl[ni][0], bl[ni][1]);
                    }
            }
        }
        cstage = (cstage == 2) ? 0 : cstage + 1;
    }

    const int crow0 = rowA0 + wm * 64;
    const int ccol0 = rowB0 + wn * 32;
#pragma unroll
    for (int mi = 0; mi < 4; mi++) {
#pragma unroll
        for (int ni = 0; ni < 4; ni++) {
            int r = crow0 + mi * 16 + (lane >> 2);
            int c = ccol0 + ni * 8 + (lane & 3) * 2;
            float b0 = bias[c], b1 = bias[c + 1];
            float* d = acc[mi][ni];
            *reinterpret_cast<float2*>(C + (size_t)r * OUTc + c) =
                make_float2(d[0] + b0, d[1] + b1);
            *reinterpret_cast<float2*>(C + (size_t)(r + 8) * OUTc + c) =
                make_float2(d[2] + b0, d[3] + b1);
        }
    }
}

// ---------------- LR@vs with 4-way K-split (R8 + occupancy fix) ----------------
__global__ void __launch_bounds__(256, 2)
gemm_lr1_kernel(const __half* __restrict__ Ah, const __half* __restrict__ Al,
                const __half* __restrict__ Bh, const __half* __restrict__ Bl) {
    constexpr int BK = 32;
    constexpr int KT = 32;               // 1024 / 32
    extern __shared__ uint4 Sd[];
    const int tid = threadIdx.x;
    const int rowA0 = blockIdx.y * 128;
    const int kz = blockIdx.z;
    const int kbase = kz * (Dc / 4);
    float* out = g_tmp4[kz];

    auto load_tile = [&](int stage, int kt) {
        const int k0 = kbase + kt * BK;
        const int so = stage * 2048;
#pragma unroll
        for (int i = tid; i < 512; i += 256) {
            int r = i >> 2, c = i & 3;
            int d = so + (r << 2) + (c ^ ((r >> 1) & 3));
            size_t srcA = (size_t)(rowA0 + r) * Dc + k0 + c * 8;
            cp_async16(smem_u32(&Sd[d]), Ah + srcA);
            cp_async16(smem_u32(&Sd[d + 512]), Al + srcA);
            size_t srcB = (size_t)r * Dc + k0 + c * 8;   // rowB0 = 0
            cp_async16(smem_u32(&Sd[d + 1024]), Bh + srcB);
            cp_async16(smem_u32(&Sd[d + 1536]), Bl + srcB);
        }
        cp_commit();
    };

    const int warp = tid >> 5, lane = tid & 31;
    const int wm = warp & 1;
    const int wn = warp >> 1;

    float acc[4][4][4];
#pragma unroll
    for (int i = 0; i < 4; i++)
#pragma unroll
        for (int j = 0; j < 4; j++)
#pragma unroll
            for (int k = 0; k < 4; k++) acc[i][j][k] = 0.f;

    load_tile(0, 0);
    load_tile(1, 1);

    int cstage = 0;
    for (int kt = 0; kt < KT; kt++) {
        if (kt >= KT - 1) cp_wait<0>(); else cp_wait<1>();
        __syncthreads();
        if (kt + 2 < KT) {
            int lstage = cstage == 0 ? 2 : cstage - 1;
            load_tile(lstage, kt + 2);
        }
        const int so = cstage * 2048;
#pragma unroll
        for (int ks = 0; ks < 2; ks++) {
            unsigned bh[4][2], bl[4][2];
#pragma unroll
            for (int nb = 0; nb < 2; nb++) {
                int n = wn * 32 + nb * 16 + (lane & 7) + ((lane >> 4) << 3);
                int kc = ks * 2 + ((lane >> 3) & 1);
                int idx = so + 1024 + (n << 2) + (kc ^ ((n >> 1) & 3));
                unsigned r0, r1, r2, r3;
                ldmatrix_x4(r0, r1, r2, r3, smem_u32(&Sd[idx]));
                bh[nb * 2][0] = r0;     bh[nb * 2][1] = r1;
                bh[nb * 2 + 1][0] = r2; bh[nb * 2 + 1][1] = r3;
                ldmatrix_x4(r0, r1, r2, r3, smem_u32(&Sd[idx + 512]));
                bl[nb * 2][0] = r0;     bl[nb * 2][1] = r1;
                bl[nb * 2 + 1][0] = r2; bl[nb * 2 + 1][1] = r3;
            }
#pragma unroll
            for (int mp = 0; mp < 2; mp++) {
                unsigned ah[2][4], al[2][4];
#pragma unroll
                for (int m2 = 0; m2 < 2; m2++) {
                    int mi = mp * 2 + m2;
                    int m = wm * 64 + mi * 16 + (lane & 15);
                    int kc = ks * 2 + (lane >> 4);
                    int idx = so + (m << 2) + (kc ^ ((m >> 1) & 3));
                    ldmatrix_x4(ah[m2][0], ah[m2][1], ah[m2][2], ah[m2][3], smem_u32(&Sd[idx]));
                    ldmatrix_x4(al[m2][0], al[m2][1], al[m2][2], al[m2][3], smem_u32(&Sd[idx + 512]));
                }
#pragma unroll
                for (int m2 = 0; m2 < 2; m2++)
#pragma unroll
                    for (int ni = 0; ni < 4; ni++) {
                        float* d = acc[mp * 2 + m2][ni];
                        mma16816(d[0], d[1], d[2], d[3],
                                 ah[m2][0], ah[m2][1], ah[m2][2], ah[m2][3], bh[ni][0], bh[ni][1]);
                        mma16816(d[0], d[1], d[2], d[3],
                                 al[m2][0], al[m2][1], al[m2][2], al[m2][3], bh[ni][0], bh[ni][1]);
                        mma16816(d[0], d[1], d[2], d[3],
                                 ah[m2][0], ah[m2][1], ah[m2][2], ah[m2][3], bl[ni][0], bl[ni][1]);
                    }
            }
        }
        cstage = (cstage == 2) ? 0 : cstage + 1;
    }

    const int crow0 = rowA0 + wm * 64;
    const int ccol0 = wn * 32;
#pragma unroll
    for (int mi = 0; mi < 4; mi++) {
#pragma unroll
        for (int ni = 0; ni < 4; ni++) {
            int r = crow0 + mi * 16 + (lane >> 2);
            int c = ccol0 + ni * 8 + (lane & 3) * 2;
            float* d = acc[mi][ni];
            *reinterpret_cast<float2*>(out + (size_t)r * RANKc + c) = make_float2(d[0], d[1]);
            *reinterpret_cast<float2*>(out + (size_t)(r + 8) * RANKc + c) = make_float2(d[2], d[3]);
        }
    }
}

// ---------------- launch ----------------
extern "C" void kernel_launch(void* const* d_in, const int* in_sizes, int n_in,
                              void* d_out, int out_size) {
    const float* x         = (const float*)d_in[0];
    const float* W         = (const float*)d_in[1];
    const float* bias      = (const float*)d_in[2];
    const float* vs        = (const float*)d_in[3];
    const float* u_t       = (const float*)d_in[4];
    const float* scale_vec = (const float*)d_in[5];
    const float* threshold = (const float*)d_in[6];
    const int*   rix       = (const int*)d_in[7];

    void *pXh, *pXl, *pLRh, *pLRl, *pWhh, *pWll, *pvsh, *pvsl, *puth, *putl, *ptmph, *ptmpl;
    cudaGetSymbolAddress(&pXh,  g_Xh);
    cudaGetSymbolAddress(&pXl,  g_Xl);
    cudaGetSymbolAddress(&pLRh, g_LRh);
    cudaGetSymbolAddress(&pLRl, g_LRl);
    cudaGetSymbolAddress(&pWhh, g_Whh);
    cudaGetSymbolAddress(&pWll, g_Wll);
    cudaGetSymbolAddress(&pvsh, g_vsh);
    cudaGetSymbolAddress(&pvsl, g_vsl);
    cudaGetSymbolAddress(&puth, g_uth);
    cudaGetSymbolAddress(&putl, g_utl);
    cudaGetSymbolAddress(&ptmph, g_tmph);
    cudaGetSymbolAddress(&ptmpl, g_tmpl);

    constexpr int SMEM_LR1 = 3 * 2048 * 16; // 96 KB
    cudaFuncSetAttribute(gemm_lr1_kernel, cudaFuncAttributeMaxDynamicSharedMemorySize, SMEM_LR1);
    cudaFuncSetAttribute(gemm_main_kernel, cudaFuncAttributeMaxDynamicSharedMemorySize, MAIN_SMEM);

    // [0] fused operand conversion (W split + vs/u_t transpose-split + maxbits reset)
    convert_all_kernel<<<2560, 256>>>(W, vs, u_t);
    // [1] absmax reduction
    reduce_max_kernel<<<1184, 256>>>(x, scale_vec, threshold);
    // [2] activation fp4-quant + fp16 split
    quantize_kernel<<<MTOK, 256>>>(x, scale_vec, threshold, rix);
    // [3] tmp partials: LR @ vs, 4-way K-split
    {
        dim3 grid(1, MTOK / 128, 4);
        gemm_lr1_kernel<<<grid, 256, SMEM_LR1>>>(
            (const __half*)pLRh, (const __half*)pLRl,
            (const __half*)pvsh, (const __half*)pvsl);
    }
    // [4] reduce partials -> split-fp16 tmp
    sum_split_kernel<<<(MTOK * RANKc + 255) / 256, 256>>>();
    // [5] fused MAIN: out = Xq @ W^T + tmp @ u_t + bias  (K=4224, 128x256x32, 3-stage)
    gemm_main_kernel<<<1024, 512, MAIN_SMEM>>>(
        (const __half*)pXh, (const __half*)pXl,
        (const __half*)pWhh, (const __half*)pWll,
        (const __half*)ptmph, (const __half*)ptmpl,
        (const __half*)puth, (const __half*)putl,
        (float*)d_out, bias);
}

// round 11
// speedup vs baseline: 1.0698x; 1.0698x over previous
#include <cuda_runtime.h>
#include <cuda_fp16.h>
#include <cstdint>

#define DEV_INLINE __device__ __forceinline__

// ---------------- problem constants (fixed shapes) ----------------
constexpr int Bc = 4, Tc = 2048, Dc = 4096, OUTc = 4096, RANKc = 128, SELECTc = 128, GROUPc = 16;
constexpr int MTOK = Bc * Tc;         // 8192 token rows
constexpr int SPARSE_T = 204;         // int(2048 * (1 - 0.9))
constexpr float SCALE_CAP = 448.0f * 6.0f;
constexpr int KFUSE = Dc + RANKc;     // 4224

// ---------------- scratch (device globals) ----------------
__device__ __half  g_Xh [(size_t)MTOK * Dc];
__device__ __half  g_Xl [(size_t)MTOK * Dc];
__device__ __half  g_LRh[(size_t)MTOK * Dc];
__device__ __half  g_LRl[(size_t)MTOK * Dc];
__device__ __half  g_Whh[(size_t)OUTc * Dc];
__device__ __half  g_Wll[(size_t)OUTc * Dc];
__device__ __half  g_vsh[(size_t)RANKc * Dc];   // vs^T [r][d]
__device__ __half  g_vsl[(size_t)RANKc * Dc];
__device__ __half  g_uth[(size_t)OUTc * RANKc]; // u_t^T [o][r]
__device__ __half  g_utl[(size_t)OUTc * RANKc];
__device__ __half  g_tmph[(size_t)MTOK * RANKc];
__device__ __half  g_tmpl[(size_t)MTOK * RANKc];
__device__ float   g_tmp4[4][(size_t)MTOK * RANKc]; // K-split partials
__device__ unsigned g_maxbits[2];

DEV_INLINE void split2(float v, __half& h, __half& l) {
    __half hh = __float2half(v);
    h = hh;
    l = __float2half(v - __half2float(hh));
}

// ---------------- fused operand conversion ----------------
__global__ void __launch_bounds__(256) convert_all_kernel(const float* __restrict__ W,
                                                          const float* __restrict__ vs,
                                                          const float* __restrict__ u_t) {
    if (blockIdx.x == 0 && threadIdx.x < 2) g_maxbits[threadIdx.x] = 0u;
    if (blockIdx.x < 2048) {
        const size_t base = (size_t)blockIdx.x * (OUTc * Dc / 2048);
        const size_t cnt = OUTc * Dc / 2048; // 8192 per block
        for (size_t k = threadIdx.x * 4; k < cnt; k += 1024) {
            float4 v4 = *reinterpret_cast<const float4*>(W + base + k);
            __half h0, l0, h1, l1, h2, l2, h3, l3;
            split2(v4.x, h0, l0); split2(v4.y, h1, l1);
            split2(v4.z, h2, l2); split2(v4.w, h3, l3);
            __half2 hh01 = __halves2half2(h0, h1), hh23 = __halves2half2(h2, h3);
            __half2 ll01 = __halves2half2(l0, l1), ll23 = __halves2half2(l2, l3);
            uint2 uh, ul;
            uh.x = *reinterpret_cast<unsigned*>(&hh01); uh.y = *reinterpret_cast<unsigned*>(&hh23);
            ul.x = *reinterpret_cast<unsigned*>(&ll01); ul.y = *reinterpret_cast<unsigned*>(&ll23);
            *reinterpret_cast<uint2*>(g_Whh + base + k) = uh;
            *reinterpret_cast<uint2*>(g_Wll + base + k) = ul;
        }
    } else {
        const int b = blockIdx.x - 2048;
        const int n = Dc * RANKc;
        const int stride = 512 * 256;
        for (int i = b * 256 + threadIdx.x; i < n; i += stride) {
            int d = i / RANKc, r = i - d * RANKc;
            __half h, l; split2(vs[i], h, l);
            g_vsh[(size_t)r * Dc + d] = h;
            g_vsl[(size_t)r * Dc + d] = l;
        }
        for (int i = b * 256 + threadIdx.x; i < n; i += stride) {
            int r = i / OUTc, o = i - r * OUTc;
            __half h, l; split2(u_t[i], h, l);
            g_uth[(size_t)o * RANKc + r] = h;
            g_utl[(size_t)o * RANKc + r] = l;
        }
    }
}

__global__ void reduce_max_kernel(const float* __restrict__ x,
                                  const float* __restrict__ scale_vec,
                                  const float* __restrict__ threshold) {
    const float thr = threshold[0];
    float mpre = 0.f, mdec = 0.f;
    const size_t n4 = (size_t)MTOK * Dc / 4;
    for (size_t i4 = (size_t)blockIdx.x * blockDim.x + threadIdx.x; i4 < n4;
         i4 += (size_t)gridDim.x * blockDim.x) {
        size_t i = i4 * 4;
        int d = (int)(i & (Dc - 1));
        int t = (int)((i >> 12) & (Tc - 1));
        float4 v = *reinterpret_cast<const float4*>(x + i);
        if (t < SPARSE_T) {
            mpre = fmaxf(mpre, fmaxf(fmaxf(fabsf(v.x), fabsf(v.y)), fmaxf(fabsf(v.z), fabsf(v.w))));
        } else {
            float4 sv = *reinterpret_cast<const float4*>(scale_vec + d);
            if (fabsf(v.x * sv.x) > thr) mdec = fmaxf(mdec, fabsf(v.x));
            if (fabsf(v.y * sv.y) > thr) mdec = fmaxf(mdec, fabsf(v.y));
            if (fabsf(v.z * sv.z) > thr) mdec = fmaxf(mdec, fabsf(v.z));
            if (fabsf(v.w * sv.w) > thr) mdec = fmaxf(mdec, fabsf(v.w));
        }
    }
#pragma unroll
    for (int o = 16; o; o >>= 1) {
        mpre = fmaxf(mpre, __shfl_xor_sync(0xffffffffu, mpre, o));
        mdec = fmaxf(mdec, __shfl_xor_sync(0xffffffffu, mdec, o));
    }
    __shared__ float spre[8], sdec[8];
    int w = threadIdx.x >> 5;
    if ((threadIdx.x & 31) == 0) { spre[w] = mpre; sdec[w] = mdec; }
    __syncthreads();
    if (threadIdx.x == 0) {
        float a = spre[0], b = sdec[0];
        for (int i = 1; i < (int)(blockDim.x >> 5); i++) {
            a = fmaxf(a, spre[i]); b = fmaxf(b, sdec[i]);
        }
        atomicMax(&g_maxbits[0], __float_as_uint(a));
        atomicMax(&g_maxbits[1], __float_as_uint(b));
    }
}

DEV_INLINE float fp4_mag(float a) {
    return a > 2.5f ? (a > 3.5f ? (a > 5.0f ? 6.0f : 4.0f) : 3.0f)
                    : (a > 1.25f ? (a > 1.75f ? 2.0f : 1.5f)
                                 : (a > 0.75f ? 1.0f : (a > 0.25f ? 0.5f : 0.0f)));
}

__global__ void __launch_bounds__(256) quantize_kernel(const float* __restrict__ x,
                                                       const float* __restrict__ scale_vec,
                                                       const float* __restrict__ threshold,
                                                       const int* __restrict__ rix) {
    __shared__ float  sx[Dc];
    __shared__ int    sri[Dc];

    const int tok = blockIdx.x;
    const int t = tok & (Tc - 1);
    const bool decode = (t >= SPARSE_T);
    const float thr = threshold[0];
    const float s = fmaxf(__uint_as_float(g_maxbits[decode ? 1 : 0]) / SCALE_CAP, 1e-12f);
    const float inv_s = 1.0f / s;
    const float* xrow = x + (size_t)tok * Dc;
    const int tid = threadIdx.x;

    __half* lrh = g_LRh + (size_t)tok * Dc;
    __half* lrl = g_LRl + (size_t)tok * Dc;

#pragma unroll
    for (int it = 0; it < 4; it++) {
        int i = it * 1024 + tid * 4;
        float4 v = *reinterpret_cast<const float4*>(xrow + i);
        *reinterpret_cast<int4*>(sri + i) = *reinterpret_cast<const int4*>(rix + i);
        float4 masked, lr;
        if (decode) {
            float4 sv = *reinterpret_cast<const float4*>(scale_vec + i);
            bool m0 = fabsf(v.x * sv.x) > thr, m1 = fabsf(v.y * sv.y) > thr;
            bool m2 = fabsf(v.z * sv.z) > thr, m3 = fabsf(v.w * sv.w) > thr;
            masked = make_float4(m0 ? v.x : 0.f, m1 ? v.y : 0.f, m2 ? v.z : 0.f, m3 ? v.w : 0.f);
            lr     = make_float4(m0 ? 0.f : v.x, m1 ? 0.f : v.y, m2 ? 0.f : v.z, m3 ? 0.f : v.w);
        } else {
            masked = v; lr = make_float4(0.f, 0.f, 0.f, 0.f);
        }
        *reinterpret_cast<float4*>(sx + i) = masked;
        __half h0, l0, h1, l1, h2, l2, h3, l3;
        split2(lr.x, h0, l0); split2(lr.y, h1, l1);
        split2(lr.z, h2, l2); split2(lr.w, h3, l3);
        __half2 hh01 = __halves2half2(h0, h1), hh23 = __halves2half2(h2, h3);
        __half2 ll01 = __halves2half2(l0, l1), ll23 = __halves2half2(l2, l3);
        uint2 uh, ul;
        uh.x = *reinterpret_cast<unsigned*>(&hh01); uh.y = *reinterpret_cast<unsigned*>(&hh23);
        ul.x = *reinterpret_cast<unsigned*>(&ll01); ul.y = *reinterpret_cast<unsigned*>(&ll23);
        *reinterpret_cast<uint2*>(lrh + i) = uh;
        *reinterpret_cast<uint2*>(lrl + i) = ul;
    }
    __syncthreads();

    if (tid < 8) {
#pragma unroll
        for (int k = 0; k < 16; k++) {
            int ri = sri[tid * 16 + k];
            float xr = sx[ri] * inv_s;
            sx[ri] = xr * s;
        }
    } else {
        const int j0 = SELECTc + (tid - 8) * GROUPc;
        float gmax = 0.f;
#pragma unroll
        for (int k = 0; k < GROUPc; k++) {
            float v = sx[sri[j0 + k]] * inv_s;
            gmax = fmaxf(gmax, fabsf(v));
        }
        float gs, inv_gs;
        if (gmax > 0.f) { gs = gmax / 6.0f; inv_gs = 6.0f / gmax; }
        else            { gs = 1.0f;       inv_gs = 1.0f; }
#pragma unroll
        for (int k = 0; k < GROUPc; k++) {
            int ri = sri[j0 + k];
            float v = sx[ri] * inv_s;
            float r = v * inv_gs;
            float q = fp4_mag(fabsf(r));
            q = (r < 0.f) ? -q : q;
            sx[ri] = (q * gs) * s;
        }
    }
    __syncthreads();

    __half* xh = g_Xh + (size_t)tok * Dc;
    __half* xl = g_Xl + (size_t)tok * Dc;
#pragma unroll
    for (int it = 0; it < 4; it++) {
        int i = it * 1024 + tid * 4;
        float4 v = *reinterpret_cast<const float4*>(sx + i);
        __half h0, l0, h1, l1, h2, l2, h3, l3;
        split2(v.x, h0, l0); split2(v.y, h1, l1);
        split2(v.z, h2, l2); split2(v.w, h3, l3);
        __half2 hh01 = __halves2half2(h0, h1), hh23 = __halves2half2(h2, h3);
        __half2 ll01 = __halves2half2(l0, l1), ll23 = __halves2half2(l2, l3);
        uint2 uh, ul;
        uh.x = *reinterpret_cast<unsigned*>(&hh01); uh.y = *reinterpret_cast<unsigned*>(&hh23);
        ul.x = *reinterpret_cast<unsigned*>(&ll01); ul.y = *reinterpret_cast<unsigned*>(&ll23);
        *reinterpret_cast<uint2*>(xh + i) = uh;
        *reinterpret_cast<uint2*>(xl + i) = ul;
    }
}

__global__ void sum_split_kernel() {
    int i = blockIdx.x * blockDim.x + threadIdx.x;
    if (i < MTOK * RANKc) {
        float s = g_tmp4[0][i] + g_tmp4[1][i] + g_tmp4[2][i] + g_tmp4[3][i];
        __half h, l; split2(s, h, l);
        g_tmph[i] = h; g_tmpl[i] = l;
    }
}

// ---------------- PTX helpers ----------------
DEV_INLINE unsigned smem_u32(const void* p) { return (unsigned)__cvta_generic_to_shared(p); }

DEV_INLINE void cp_async16(unsigned dst, const void* src) {
    asm volatile("cp.async.cg.shared.global [%0], [%1], 16;\n" :: "r"(dst), "l"(src));
}
DEV_INLINE void cp_commit() { asm volatile("cp.async.commit_group;\n"); }
template <int N> DEV_INLINE void cp_wait() { asm volatile("cp.async.wait_group %0;\n" :: "n"(N)); }

DEV_INLINE void ldmatrix_x4(unsigned& r0, unsigned& r1, unsigned& r2, unsigned& r3, unsigned addr) {
    asm volatile("ldmatrix.sync.aligned.m8n8.x4.shared.b16 {%0,%1,%2,%3}, [%4];\n"
                 : "=r"(r0), "=r"(r1), "=r"(r2), "=r"(r3) : "r"(addr));
}
DEV_INLINE void mma16816(float& d0, float& d1, float& d2, float& d3,
                         unsigned a0, unsigned a1, unsigned a2, unsigned a3,
                         unsigned b0, unsigned b1) {
    asm volatile("mma.sync.aligned.m16n8k16.row.col.f32.f16.f16.f32 "
                 "{%0,%1,%2,%3}, {%4,%5,%6,%7}, {%8,%9}, {%0,%1,%2,%3};\n"
                 : "+f"(d0), "+f"(d1), "+f"(d2), "+f"(d3)
                 : "r"(a0), "r"(a1), "r"(a2), "r"(a3), "r"(b0), "r"(b1));
}

// ================= fused main GEMM (R8-proven config) =================
// 256 threads, 128x128x32 tile, 3-stage (96KB), distance-2, single barrier,
// 2 CTAs/SM. Register-budgeted mainloop (B resident per ks, A in mi-pairs).
constexpr int MAIN_KT = KFUSE / 32;           // 132
constexpr int MAIN_SMEM = 3 * 2048 * 16;      // 96 KB

__global__ void __launch_bounds__(256, 2)
gemm_main_kernel(const __half* __restrict__ Ah, const __half* __restrict__ Al,
                 const __half* __restrict__ Bh, const __half* __restrict__ Bl,
                 const __half* __restrict__ Eah, const __half* __restrict__ Eal,
                 const __half* __restrict__ Ebh, const __half* __restrict__ Ebl,
                 float* __restrict__ C, const float* __restrict__ bias) {
    extern __shared__ uint4 S[];
    const int tid = threadIdx.x;

    // supertile raster: groups of 32 M-tiles x 8 N-tiles
    const int bid = blockIdx.x;
    const int gid = bid >> 8, wit = bid & 255;
    const int mt = (gid & 1) * 32 + (wit & 31);
    const int nt = (gid >> 1) * 8 + (wit >> 5);
    const int rowA0 = mt * 128;
    const int rowB0 = nt * 128;

    auto load_tile = [&](int stage, int kt) {
        const int so = stage * 2048;
#pragma unroll
        for (int i = tid; i < 512; i += 256) {
            int r = i >> 2, c = i & 3;
            int d = so + (r << 2) + (c ^ ((r >> 1) & 3));
            if (kt < Dc / 32) {
                size_t srcA = (size_t)(rowA0 + r) * Dc + kt * 32 + c * 8;
                cp_async16(smem_u32(&S[d]), Ah + srcA);
                cp_async16(smem_u32(&S[d + 512]), Al + srcA);
                size_t srcB = (size_t)(rowB0 + r) * Dc + kt * 32 + c * 8;
                cp_async16(smem_u32(&S[d + 1024]), Bh + srcB);
                cp_async16(smem_u32(&S[d + 1536]), Bl + srcB);
            } else {
                int k0 = (kt - Dc / 32) * 32;
                size_t srcA = (size_t)(rowA0 + r) * RANKc + k0 + c * 8;
                cp_async16(smem_u32(&S[d]), Eah + srcA);
                cp_async16(smem_u32(&S[d + 512]), Eal + srcA);
                size_t srcB = (size_t)(rowB0 + r) * RANKc + k0 + c * 8;
                cp_async16(smem_u32(&S[d + 1024]), Ebh + srcB);
                cp_async16(smem_u32(&S[d + 1536]), Ebl + srcB);
            }
        }
        cp_commit();
    };

    const int warp = tid >> 5, lane = tid & 31;
    const int wm = warp & 1;    // 2 warp-rows of 64
    const int wn = warp >> 1;   // 4 warp-cols of 32

    float acc[4][4][4];
#pragma unroll
    for (int i = 0; i < 4; i++)
#pragma unroll
        for (int j = 0; j < 4; j++)
#pragma unroll
            for (int k = 0; k < 4; k++) acc[i][j][k] = 0.f;

    load_tile(0, 0);
    load_tile(1, 1);

    int cstage = 0;
    for (int kt = 0; kt < MAIN_KT; kt++) {
        if (kt >= MAIN_KT - 1) cp_wait<0>(); else cp_wait<1>();
        __syncthreads();
        // issue next loads BEFORE compute (target stage consumed at kt-1)
        if (kt + 2 < MAIN_KT) {
            int lstage = cstage == 0 ? 2 : cstage - 1;
            load_tile(lstage, kt + 2);
        }
        const int so = cstage * 2048;
#pragma unroll
        for (int ks = 0; ks < 2; ks++) {
            unsigned bh[4][2], bl[4][2];
#pragma unroll
            for (int nb = 0; nb < 2; nb++) {
                int n = wn * 32 + nb * 16 + (lane & 7) + ((lane >> 4) << 3);
                int kc = ks * 2 + ((lane >> 3) & 1);
                int idx = so + 1024 + (n << 2) + (kc ^ ((n >> 1) & 3));
                unsigned r0, r1, r2, r3;
                ldmatrix_x4(r0, r1, r2, r3, smem_u32(&S[idx]));
                bh[nb * 2][0] = r0;     bh[nb * 2][1] = r1;
                bh[nb * 2 + 1][0] = r2; bh[nb * 2 + 1][1] = r3;
                ldmatrix_x4(r0, r1, r2, r3, smem_u32(&S[idx + 512]));
                bl[nb * 2][0] = r0;     bl[nb * 2][1] = r1;
                bl[nb * 2 + 1][0] = r2; bl[nb * 2 + 1][1] = r3;
            }
#pragma unroll
            for (int mp = 0; mp < 2; mp++) {
                unsigned ah[2][4], al[2][4];
#pragma unroll
                for (int m2 = 0; m2 < 2; m2++) {
                    int mi = mp * 2 + m2;
                    int m = wm * 64 + mi * 16 + (lane & 15);
                    int kc = ks * 2 + (lane >> 4);
                    int idx = so + (m << 2) + (kc ^ ((m >> 1) & 3));
                    ldmatrix_x4(ah[m2][0], ah[m2][1], ah[m2][2], ah[m2][3], smem_u32(&S[idx]));
                    ldmatrix_x4(al[m2][0], al[m2][1], al[m2][2], al[m2][3], smem_u32(&S[idx + 512]));
                }
#pragma unroll
                for (int m2 = 0; m2 < 2; m2++)
#pragma unroll
                    for (int ni = 0; ni < 4; ni++) {
                        float* d = acc[mp * 2 + m2][ni];
                        mma16816(d[0], d[1], d[2], d[3],
                                 ah[m2][0], ah[m2][1], ah[m2][2], ah[m2][3], bh[ni][0], bh[ni][1]);
                        mma16816(d[0], d[1], d[2], d[3],
                                 al[m2][0], al[m2][1], al[m2][2], al[m2][3], bh[ni][0], bh[ni][1]);
                        mma16816(d[0], d[1], d[2], d[3],
                                 ah[m2][0], ah[m2][1], ah[m2][2], ah[m2][3], bl[ni][0], bl[ni][1]);
                    }
            }
        }
        cstage = (cstage == 2) ? 0 : cstage + 1;
    }

    const int crow0 = rowA0 + wm * 64;
    const int ccol0 = rowB0 + wn * 32;
#pragma unroll
    for (int mi = 0; mi < 4; mi++) {
#pragma unroll
        for (int ni = 0; ni < 4; ni++) {
            int r = crow0 + mi * 16 + (lane >> 2);
            int c = ccol0 + ni * 8 + (lane & 3) * 2;
            float b0 = bias[c], b1 = bias[c + 1];
            float* d = acc[mi][ni];
            *reinterpret_cast<float2*>(C + (size_t)r * OUTc + c) =
                make_float2(d[0] + b0, d[1] + b1);
            *reinterpret_cast<float2*>(C + (size_t)(r + 8) * OUTc + c) =
                make_float2(d[2] + b0, d[3] + b1);
        }
    }
}

// ---------------- LR@vs with 4-way K-split (R8 + validated occupancy fix) ----------------
__global__ void __launch_bounds__(256, 2)
gemm_lr1_kernel(const __half* __restrict__ Ah, const __half* __restrict__ Al,
                const __half* __restrict__ Bh, const __half* __restrict__ Bl) {
    constexpr int BK = 32;
    constexpr int KT = 32;               // 1024 / 32
    extern __shared__ uint4 Sd[];
    const int tid = threadIdx.x;
    const int rowA0 = blockIdx.y * 128;
    const int kz = blockIdx.z;
    const int kbase = kz * (Dc / 4);
    float* out = g_tmp4[kz];

    auto load_tile = [&](int stage, int kt) {
        const int k0 = kbase + kt * BK;
        const int so = stage * 2048;
#pragma unroll
        for (int i = tid; i < 512; i += 256) {
            int r = i >> 2, c = i & 3;
            int d = so + (r << 2) + (c ^ ((r >> 1) & 3));
            size_t srcA = (size_t)(rowA0 + r) * Dc + k0 + c * 8;
            cp_async16(smem_u32(&Sd[d]), Ah + srcA);
            cp_async16(smem_u32(&Sd[d + 512]), Al + srcA);
            size_t srcB = (size_t)r * Dc + k0 + c * 8;   // rowB0 = 0
            cp_async16(smem_u32(&Sd[d + 1024]), Bh + srcB);
            cp_async16(smem_u32(&Sd[d + 1536]), Bl + srcB);
        }
        cp_commit();
    };

    const int warp = tid >> 5, lane = tid & 31;
    const int wm = warp & 1;
    const int wn = warp >> 1;

    float acc[4][4][4];
#pragma unroll
    for (int i = 0; i < 4; i++)
#pragma unroll
        for (int j = 0; j < 4; j++)
#pragma unroll
            for (int k = 0; k < 4; k++) acc[i][j][k] = 0.f;

    load_tile(0, 0);
    load_tile(1, 1);

    int cstage = 0;
    for (int kt = 0; kt < KT; kt++) {
        if (kt >= KT - 1) cp_wait<0>(); else cp_wait<1>();
        __syncthreads();
        if (kt + 2 < KT) {
            int lstage = cstage == 0 ? 2 : cstage - 1;
            load_tile(lstage, kt + 2);
        }
        const int so = cstage * 2048;
#pragma unroll
        for (int ks = 0; ks < 2; ks++) {
            unsigned bh[4][2], bl[4][2];
#pragma unroll
            for (int nb = 0; nb < 2; nb++) {
                int n = wn * 32 + nb * 16 + (lane & 7) + ((lane >> 4) << 3);
                int kc = ks * 2 + ((lane >> 3) & 1);
                int idx = so + 1024 + (n << 2) + (kc ^ ((n >> 1) & 3));
                unsigned r0, r1, r2, r3;
                ldmatrix_x4(r0, r1, r2, r3, smem_u32(&Sd[idx]));
                bh[nb * 2][0] = r0;     bh[nb * 2][1] = r1;
                bh[nb * 2 + 1][0] = r2; bh[nb * 2 + 1][1] = r3;
                ldmatrix_x4(r0, r1, r2, r3, smem_u32(&Sd[idx + 512]));
                bl[nb * 2][0] = r0;     bl[nb * 2][1] = r1;
                bl[nb * 2 + 1][0] = r2; bl[nb * 2 + 1][1] = r3;
            }
#pragma unroll
            for (int mp = 0; mp < 2; mp++) {
                unsigned ah[2][4], al[2][4];
#pragma unroll
                for (int m2 = 0; m2 < 2; m2++) {
                    int mi = mp * 2 + m2;
                    int m = wm * 64 + mi * 16 + (lane & 15);
                    int kc = ks * 2 + (lane >> 4);
                    int idx = so + (m << 2) + (kc ^ ((m >> 1) & 3));
                    ldmatrix_x4(ah[m2][0], ah[m2][1], ah[m2][2], ah[m2][3], smem_u32(&Sd[idx]));
                    ldmatrix_x4(al[m2][0], al[m2][1], al[m2][2], al[m2][3], smem_u32(&Sd[idx + 512]));
                }
#pragma unroll
                for (int m2 = 0; m2 < 2; m2++)
#pragma unroll
                    for (int ni = 0; ni < 4; ni++) {
                        float* d = acc[mp * 2 + m2][ni];
                        mma16816(d[0], d[1], d[2], d[3],
                                 ah[m2][0], ah[m2][1], ah[m2][2], ah[m2][3], bh[ni][0], bh[ni][1]);
                        mma16816(d[0], d[1], d[2], d[3],
                                 al[m2][0], al[m2][1], al[m2][2], al[m2][3], bh[ni][0], bh[ni][1]);
                        mma16816(d[0], d[1], d[2], d[3],
                                 ah[m2][0], ah[m2][1], ah[m2][2], ah[m2][3], bl[ni][0], bl[ni][1]);
                    }
            }
        }
        cstage = (cstage == 2) ? 0 : cstage + 1;
    }

    const int crow0 = rowA0 + wm * 64;
    const int ccol0 = wn * 32;
#pragma unroll
    for (int mi = 0; mi < 4; mi++) {
#pragma unroll
        for (int ni = 0; ni < 4; ni++) {
            int r = crow0 + mi * 16 + (lane >> 2);
            int c = ccol0 + ni * 8 + (lane & 3) * 2;
            float* d = acc[mi][ni];
            *reinterpret_cast<float2*>(out + (size_t)r * RANKc + c) = make_float2(d[0], d[1]);
            *reinterpret_cast<float2*>(out + (size_t)(r + 8) * RANKc + c) = make_float2(d[2], d[3]);
        }
    }
}

// ---------------- launch ----------------
extern "C" void kernel_launch(void* const* d_in, const int* in_sizes, int n_in,
                              void* d_out, int out_size) {
    const float* x         = (const float*)d_in[0];
    const float* W         = (const float*)d_in[1];
    const float* bias      = (const float*)d_in[2];
    const float* vs        = (const float*)d_in[3];
    const float* u_t       = (const float*)d_in[4];
    const float* scale_vec = (const float*)d_in[5];
    const float* threshold = (const float*)d_in[6];
    const int*   rix       = (const int*)d_in[7];

    void *pXh, *pXl, *pLRh, *pLRl, *pWhh, *pWll, *pvsh, *pvsl, *puth, *putl, *ptmph, *ptmpl;
    cudaGetSymbolAddress(&pXh,  g_Xh);
    cudaGetSymbolAddress(&pXl,  g_Xl);
    cudaGetSymbolAddress(&pLRh, g_LRh);
    cudaGetSymbolAddress(&pLRl, g_LRl);
    cudaGetSymbolAddress(&pWhh, g_Whh);
    cudaGetSymbolAddress(&pWll, g_Wll);
    cudaGetSymbolAddress(&pvsh, g_vsh);
    cudaGetSymbolAddress(&pvsl, g_vsl);
    cudaGetSymbolAddress(&puth, g_uth);
    cudaGetSymbolAddress(&putl, g_utl);
    cudaGetSymbolAddress(&ptmph, g_tmph);
    cudaGetSymbolAddress(&ptmpl, g_tmpl);

    constexpr int SMEM_LR1 = 3 * 2048 * 16; // 96 KB
    cudaFuncSetAttribute(gemm_lr1_kernel, cudaFuncAttributeMaxDynamicSharedMemorySize, SMEM_LR1);
    cudaFuncSetAttribute(gemm_main_kernel, cudaFuncAttributeMaxDynamicSharedMemorySize, MAIN_SMEM);

    // [0] fused operand conversion (W split + vs/u_t transpose-split + maxbits reset)
    convert_all_kernel<<<2560, 256>>>(W, vs, u_t);
    // [1] absmax reduction
    reduce_max_kernel<<<1184, 256>>>(x, scale_vec, threshold);
    // [2] activation fp4-quant + fp16 split
    quantize_kernel<<<MTOK, 256>>>(x, scale_vec, threshold, rix);
    // [3] tmp partials: LR @ vs, 4-way K-split
    {
        dim3 grid(1, MTOK / 128, 4);
        gemm_lr1_kernel<<<grid, 256, SMEM_LR1>>>(
            (const __half*)pLRh, (const __half*)pLRl,
            (const __half*)pvsh, (const __half*)pvsl);
    }
    // [4] reduce partials -> split-fp16 tmp
    sum_split_kernel<<<(MTOK * RANKc + 255) / 256, 256>>>();
    // [5] fused MAIN: out = Xq @ W^T + tmp @ u_t + bias  (K=4224, R8 config)
    gemm_main_kernel<<<2048, 256, MAIN_SMEM>>>(
        (const __half*)pXh, (const __half*)pXl,
        (const __half*)pWhh, (const __half*)pWll,
        (const __half*)ptmph, (const __half*)ptmpl,
        (const __half*)puth, (const __half*)putl,
        (float*)d_out, bias);
}

// round 12
// speedup vs baseline: 1.0752x; 1.0051x over previous
#include <cuda_runtime.h>
#include <cuda_fp16.h>
#include <cstdint>

#define DEV_INLINE __device__ __forceinline__

// ---------------- problem constants (fixed shapes) ----------------
constexpr int Bc = 4, Tc = 2048, Dc = 4096, OUTc = 4096, RANKc = 128, SELECTc = 128, GROUPc = 16;
constexpr int MTOK = Bc * Tc;         // 8192 token rows
constexpr int SPARSE_T = 204;         // int(2048 * (1 - 0.9))
constexpr float SCALE_CAP = 448.0f * 6.0f;
constexpr int KFUSE = Dc + RANKc;     // 4224

// ---------------- scratch (device globals) ----------------
__device__ __half  g_Xh [(size_t)MTOK * Dc];
__device__ __half  g_Xl [(size_t)MTOK * Dc];
__device__ __half  g_LRh[(size_t)MTOK * Dc];
__device__ __half  g_LRl[(size_t)MTOK * Dc];
__device__ __half  g_Whh[(size_t)OUTc * Dc];
__device__ __half  g_Wll[(size_t)OUTc * Dc];
__device__ __half  g_vsh[(size_t)RANKc * Dc];   // vs^T [r][d]
__device__ __half  g_vsl[(size_t)RANKc * Dc];
__device__ __half  g_uth[(size_t)OUTc * RANKc]; // u_t^T [o][r]
__device__ __half  g_utl[(size_t)OUTc * RANKc];
__device__ __half  g_tmph[(size_t)MTOK * RANKc];
__device__ __half  g_tmpl[(size_t)MTOK * RANKc];
__device__ float   g_tmp4[4][(size_t)MTOK * RANKc]; // K-split partials
__device__ unsigned g_maxbits[2];

DEV_INLINE void split2(float v, __half& h, __half& l) {
    __half hh = __float2half(v);
    h = hh;
    l = __float2half(v - __half2float(hh));
}

// ---------------- fused operand conversion ----------------
__global__ void __launch_bounds__(256) convert_all_kernel(const float* __restrict__ W,
                                                          const float* __restrict__ vs,
                                                          const float* __restrict__ u_t) {
    if (blockIdx.x == 0 && threadIdx.x < 2) g_maxbits[threadIdx.x] = 0u;
    if (blockIdx.x < 2048) {
        const size_t base = (size_t)blockIdx.x * (OUTc * Dc / 2048);
        const size_t cnt = OUTc * Dc / 2048; // 8192 per block
        for (size_t k = threadIdx.x * 4; k < cnt; k += 1024) {
            float4 v4 = *reinterpret_cast<const float4*>(W + base + k);
            __half h0, l0, h1, l1, h2, l2, h3, l3;
            split2(v4.x, h0, l0); split2(v4.y, h1, l1);
            split2(v4.z, h2, l2); split2(v4.w, h3, l3);
            __half2 hh01 = __halves2half2(h0, h1), hh23 = __halves2half2(h2, h3);
            __half2 ll01 = __halves2half2(l0, l1), ll23 = __halves2half2(l2, l3);
            uint2 uh, ul;
            uh.x = *reinterpret_cast<unsigned*>(&hh01); uh.y = *reinterpret_cast<unsigned*>(&hh23);
            ul.x = *reinterpret_cast<unsigned*>(&ll01); ul.y = *reinterpret_cast<unsigned*>(&ll23);
            *reinterpret_cast<uint2*>(g_Whh + base + k) = uh;
            *reinterpret_cast<uint2*>(g_Wll + base + k) = ul;
        }
    } else {
        const int b = blockIdx.x - 2048;
        const int n = Dc * RANKc;
        const int stride = 512 * 256;
        for (int i = b * 256 + threadIdx.x; i < n; i += stride) {
            int d = i / RANKc, r = i - d * RANKc;
            __half h, l; split2(vs[i], h, l);
            g_vsh[(size_t)r * Dc + d] = h;
            g_vsl[(size_t)r * Dc + d] = l;
        }
        for (int i = b * 256 + threadIdx.x; i < n; i += stride) {
            int r = i / OUTc, o = i - r * OUTc;
            __half h, l; split2(u_t[i], h, l);
            g_uth[(size_t)o * RANKc + r] = h;
            g_utl[(size_t)o * RANKc + r] = l;
        }
    }
}

__global__ void reduce_max_kernel(const float* __restrict__ x,
                                  const float* __restrict__ scale_vec,
                                  const float* __restrict__ threshold) {
    const float thr = threshold[0];
    float mpre = 0.f, mdec = 0.f;
    const size_t n4 = (size_t)MTOK * Dc / 4;
    for (size_t i4 = (size_t)blockIdx.x * blockDim.x + threadIdx.x; i4 < n4;
         i4 += (size_t)gridDim.x * blockDim.x) {
        size_t i = i4 * 4;
        int d = (int)(i & (Dc - 1));
        int t = (int)((i >> 12) & (Tc - 1));
        float4 v = *reinterpret_cast<const float4*>(x + i);
        if (t < SPARSE_T) {
            mpre = fmaxf(mpre, fmaxf(fmaxf(fabsf(v.x), fabsf(v.y)), fmaxf(fabsf(v.z), fabsf(v.w))));
        } else {
            float4 sv = *reinterpret_cast<const float4*>(scale_vec + d);
            if (fabsf(v.x * sv.x) > thr) mdec = fmaxf(mdec, fabsf(v.x));
            if (fabsf(v.y * sv.y) > thr) mdec = fmaxf(mdec, fabsf(v.y));
            if (fabsf(v.z * sv.z) > thr) mdec = fmaxf(mdec, fabsf(v.z));
            if (fabsf(v.w * sv.w) > thr) mdec = fmaxf(mdec, fabsf(v.w));
        }
    }
#pragma unroll
    for (int o = 16; o; o >>= 1) {
        mpre = fmaxf(mpre, __shfl_xor_sync(0xffffffffu, mpre, o));
        mdec = fmaxf(mdec, __shfl_xor_sync(0xffffffffu, mdec, o));
    }
    __shared__ float spre[8], sdec[8];
    int w = threadIdx.x >> 5;
    if ((threadIdx.x & 31) == 0) { spre[w] = mpre; sdec[w] = mdec; }
    __syncthreads();
    if (threadIdx.x == 0) {
        float a = spre[0], b = sdec[0];
        for (int i = 1; i < (int)(blockDim.x >> 5); i++) {
            a = fmaxf(a, spre[i]); b = fmaxf(b, sdec[i]);
        }
        atomicMax(&g_maxbits[0], __float_as_uint(a));
        atomicMax(&g_maxbits[1], __float_as_uint(b));
    }
}

DEV_INLINE float fp4_mag(float a) {
    return a > 2.5f ? (a > 3.5f ? (a > 5.0f ? 6.0f : 4.0f) : 3.0f)
                    : (a > 1.25f ? (a > 1.75f ? 2.0f : 1.5f)
                                 : (a > 0.75f ? 1.0f : (a > 0.25f ? 0.5f : 0.0f)));
}

// One block per token. rix is read straight from global (L2-resident, shared
// by all 8192 blocks) into registers -> smem halved to 16KB; launch_bounds
// caps regs for 5 CTAs/SM. Arithmetic identical to R11.
__global__ void __launch_bounds__(256, 5) quantize_kernel(const float* __restrict__ x,
                                                          const float* __restrict__ scale_vec,
                                                          const float* __restrict__ threshold,
                                                          const int* __restrict__ rix) {
    __shared__ float sx[Dc];   // 16 KB

    const int tok = blockIdx.x;
    const int t = tok & (Tc - 1);
    const bool decode = (t >= SPARSE_T);
    const float thr = threshold[0];
    const float s = fmaxf(__uint_as_float(g_maxbits[decode ? 1 : 0]) / SCALE_CAP, 1e-12f);
    const float inv_s = 1.0f / s;
    const float* xrow = x + (size_t)tok * Dc;
    const int tid = threadIdx.x;

    __half* lrh = g_LRh + (size_t)tok * Dc;
    __half* lrl = g_LRl + (size_t)tok * Dc;

    // phase 1: masked value -> sx; LR split -> global (vectorized)
#pragma unroll
    for (int it = 0; it < 4; it++) {
        int i = it * 1024 + tid * 4;
        float4 v = *reinterpret_cast<const float4*>(xrow + i);
        float4 masked, lr;
        if (decode) {
            float4 sv = *reinterpret_cast<const float4*>(scale_vec + i);
            bool m0 = fabsf(v.x * sv.x) > thr, m1 = fabsf(v.y * sv.y) > thr;
            bool m2 = fabsf(v.z * sv.z) > thr, m3 = fabsf(v.w * sv.w) > thr;
            masked = make_float4(m0 ? v.x : 0.f, m1 ? v.y : 0.f, m2 ? v.z : 0.f, m3 ? v.w : 0.f);
            lr     = make_float4(m0 ? 0.f : v.x, m1 ? 0.f : v.y, m2 ? 0.f : v.z, m3 ? 0.f : v.w);
        } else {
            masked = v; lr = make_float4(0.f, 0.f, 0.f, 0.f);
        }
        *reinterpret_cast<float4*>(sx + i) = masked;
        __half h0, l0, h1, l1, h2, l2, h3, l3;
        split2(lr.x, h0, l0); split2(lr.y, h1, l1);
        split2(lr.z, h2, l2); split2(lr.w, h3, l3);
        __half2 hh01 = __halves2half2(h0, h1), hh23 = __halves2half2(h2, h3);
        __half2 ll01 = __halves2half2(l0, l1), ll23 = __halves2half2(l2, l3);
        uint2 uh, ul;
        uh.x = *reinterpret_cast<unsigned*>(&hh01); uh.y = *reinterpret_cast<unsigned*>(&hh23);
        ul.x = *reinterpret_cast<unsigned*>(&ll01); ul.y = *reinterpret_cast<unsigned*>(&ll23);
        *reinterpret_cast<uint2*>(lrh + i) = uh;
        *reinterpret_cast<uint2*>(lrl + i) = ul;
    }
    __syncthreads();

    // phase 2: fp4 quant in reordered space; indices straight from global.
    // Each thread owns 16 consecutive reordered slots -> 4x int4 loads.
    {
        int j0 = (tid < 8) ? tid * 16 : SELECTc + (tid - 8) * GROUPc;
        int ris[16];
#pragma unroll
        for (int c = 0; c < 4; c++)
            *reinterpret_cast<int4*>(ris + c * 4) =
                *reinterpret_cast<const int4*>(rix + j0 + c * 4);

        if (tid < 8) {
#pragma unroll
            for (int k = 0; k < 16; k++) {
                int ri = ris[k];
                float xr = sx[ri] * inv_s;
                sx[ri] = xr * s;
            }
        } else {
            float gmax = 0.f;
#pragma unroll
            for (int k = 0; k < GROUPc; k++) {
                float v = sx[ris[k]] * inv_s;
                gmax = fmaxf(gmax, fabsf(v));
            }
            float gs, inv_gs;
            if (gmax > 0.f) { gs = gmax / 6.0f; inv_gs = 6.0f / gmax; }
            else            { gs = 1.0f;       inv_gs = 1.0f; }
#pragma unroll
            for (int k = 0; k < GROUPc; k++) {
                int ri = ris[k];
                float v = sx[ri] * inv_s;
                float r = v * inv_gs;
                float q = fp4_mag(fabsf(r));
                q = (r < 0.f) ? -q : q;
                sx[ri] = (q * gs) * s;
            }
        }
    }
    __syncthreads();

    // phase 3: split-fp16 writeback (vectorized)
    __half* xh = g_Xh + (size_t)tok * Dc;
    __half* xl = g_Xl + (size_t)tok * Dc;
#pragma unroll
    for (int it = 0; it < 4; it++) {
        int i = it * 1024 + tid * 4;
        float4 v = *reinterpret_cast<const float4*>(sx + i);
        __half h0, l0, h1, l1, h2, l2, h3, l3;
        split2(v.x, h0, l0); split2(v.y, h1, l1);
        split2(v.z, h2, l2); split2(v.w, h3, l3);
        __half2 hh01 = __halves2half2(h0, h1), hh23 = __halves2half2(h2, h3);
        __half2 ll01 = __halves2half2(l0, l1), ll23 = __halves2half2(l2, l3);
        uint2 uh, ul;
        uh.x = *reinterpret_cast<unsigned*>(&hh01); uh.y = *reinterpret_cast<unsigned*>(&hh23);
        ul.x = *reinterpret_cast<unsigned*>(&ll01); ul.y = *reinterpret_cast<unsigned*>(&ll23);
        *reinterpret_cast<uint2*>(xh + i) = uh;
        *reinterpret_cast<uint2*>(xl + i) = ul;
    }
}

__global__ void sum_split_kernel() {
    int i = blockIdx.x * blockDim.x + threadIdx.x;
    if (i < MTOK * RANKc) {
        float s = g_tmp4[0][i] + g_tmp4[1][i] + g_tmp4[2][i] + g_tmp4[3][i];
        __half h, l; split2(s, h, l);
        g_tmph[i] = h; g_tmpl[i] = l;
    }
}

// ---------------- PTX helpers ----------------
DEV_INLINE unsigned smem_u32(const void* p) { return (unsigned)__cvta_generic_to_shared(p); }

DEV_INLINE void cp_async16(unsigned dst, const void* src) {
    asm volatile("cp.async.cg.shared.global [%0], [%1], 16;\n" :: "r"(dst), "l"(src));
}
DEV_INLINE void cp_commit() { asm volatile("cp.async.commit_group;\n"); }
template <int N> DEV_INLINE void cp_wait() { asm volatile("cp.async.wait_group %0;\n" :: "n"(N)); }

DEV_INLINE void ldmatrix_x4(unsigned& r0, unsigned& r1, unsigned& r2, unsigned& r3, unsigned addr) {
    asm volatile("ldmatrix.sync.aligned.m8n8.x4.shared.b16 {%0,%1,%2,%3}, [%4];\n"
                 : "=r"(r0), "=r"(r1), "=r"(r2), "=r"(r3) : "r"(addr));
}
DEV_INLINE void mma16816(float& d0, float& d1, float& d2, float& d3,
                         unsigned a0, unsigned a1, unsigned a2, unsigned a3,
                         unsigned b0, unsigned b1) {
    asm volatile("mma.sync.aligned.m16n8k16.row.col.f32.f16.f16.f32 "
                 "{%0,%1,%2,%3}, {%4,%5,%6,%7}, {%8,%9}, {%0,%1,%2,%3};\n"
                 : "+f"(d0), "+f"(d1), "+f"(d2), "+f"(d3)
                 : "r"(a0), "r"(a1), "r"(a2), "r"(a3), "r"(b0), "r"(b1));
}

// ================= fused main GEMM (R8-proven config, unchanged) =================
constexpr int MAIN_KT = KFUSE / 32;           // 132
constexpr int MAIN_SMEM = 3 * 2048 * 16;      // 96 KB

__global__ void __launch_bounds__(256, 2)
gemm_main_kernel(const __half* __restrict__ Ah, const __half* __restrict__ Al,
                 const __half* __restrict__ Bh, const __half* __restrict__ Bl,
                 const __half* __restrict__ Eah, const __half* __restrict__ Eal,
                 const __half* __restrict__ Ebh, const __half* __restrict__ Ebl,
                 float* __restrict__ C, const float* __restrict__ bias) {
    extern __shared__ uint4 S[];
    const int tid = threadIdx.x;

    // supertile raster: groups of 32 M-tiles x 8 N-tiles
    const int bid = blockIdx.x;
    const int gid = bid >> 8, wit = bid & 255;
    const int mt = (gid & 1) * 32 + (wit & 31);
    const int nt = (gid >> 1) * 8 + (wit >> 5);
    const int rowA0 = mt * 128;
    const int rowB0 = nt * 128;

    auto load_tile = [&](int stage, int kt) {
        const int so = stage * 2048;
#pragma unroll
        for (int i = tid; i < 512; i += 256) {
            int r = i >> 2, c = i & 3;
            int d = so + (r << 2) + (c ^ ((r >> 1) & 3));
            if (kt < Dc / 32) {
                size_t srcA = (size_t)(rowA0 + r) * Dc + kt * 32 + c * 8;
                cp_async16(smem_u32(&S[d]), Ah + srcA);
                cp_async16(smem_u32(&S[d + 512]), Al + srcA);
                size_t srcB = (size_t)(rowB0 + r) * Dc + kt * 32 + c * 8;
                cp_async16(smem_u32(&S[d + 1024]), Bh + srcB);
                cp_async16(smem_u32(&S[d + 1536]), Bl + srcB);
            } else {
                int k0 = (kt - Dc / 32) * 32;
                size_t srcA = (size_t)(rowA0 + r) * RANKc + k0 + c * 8;
                cp_async16(smem_u32(&S[d]), Eah + srcA);
                cp_async16(smem_u32(&S[d + 512]), Eal + srcA);
                size_t srcB = (size_t)(rowB0 + r) * RANKc + k0 + c * 8;
                cp_async16(smem_u32(&S[d + 1024]), Ebh + srcB);
                cp_async16(smem_u32(&S[d + 1536]), Ebl + srcB);
            }
        }
        cp_commit();
    };

    const int warp = tid >> 5, lane = tid & 31;
    const int wm = warp & 1;    // 2 warp-rows of 64
    const int wn = warp >> 1;   // 4 warp-cols of 32

    float acc[4][4][4];
#pragma unroll
    for (int i = 0; i < 4; i++)
#pragma unroll
        for (int j = 0; j < 4; j++)
#pragma unroll
            for (int k = 0; k < 4; k++) acc[i][j][k] = 0.f;

    load_tile(0, 0);
    load_tile(1, 1);

    int cstage = 0;
    for (int kt = 0; kt < MAIN_KT; kt++) {
        if (kt >= MAIN_KT - 1) cp_wait<0>(); else cp_wait<1>();
        __syncthreads();
        if (kt + 2 < MAIN_KT) {
            int lstage = cstage == 0 ? 2 : cstage - 1;
            load_tile(lstage, kt + 2);
        }
        const int so = cstage * 2048;
#pragma unroll
        for (int ks = 0; ks < 2; ks++) {
            unsigned bh[4][2], bl[4][2];
#pragma unroll
            for (int nb = 0; nb < 2; nb++) {
                int n = wn * 32 + nb * 16 + (lane & 7) + ((lane >> 4) << 3);
                int kc = ks * 2 + ((lane >> 3) & 1);
                int idx = so + 1024 + (n << 2) + (kc ^ ((n >> 1) & 3));
                unsigned r0, r1, r2, r3;
                ldmatrix_x4(r0, r1, r2, r3, smem_u32(&S[idx]));
                bh[nb * 2][0] = r0;     bh[nb * 2][1] = r1;
                bh[nb * 2 + 1][0] = r2; bh[nb * 2 + 1][1] = r3;
                ldmatrix_x4(r0, r1, r2, r3, smem_u32(&S[idx + 512]));
                bl[nb * 2][0] = r0;     bl[nb * 2][1] = r1;
                bl[nb * 2 + 1][0] = r2; bl[nb * 2 + 1][1] = r3;
            }
#pragma unroll
            for (int mp = 0; mp < 2; mp++) {
                unsigned ah[2][4], al[2][4];
#pragma unroll
                for (int m2 = 0; m2 < 2; m2++) {
                    int mi = mp * 2 + m2;
                    int m = wm * 64 + mi * 16 + (lane & 15);
                    int kc = ks * 2 + (lane >> 4);
                    int idx = so + (m << 2) + (kc ^ ((m >> 1) & 3));
                    ldmatrix_x4(ah[m2][0], ah[m2][1], ah[m2][2], ah[m2][3], smem_u32(&S[idx]));
                    ldmatrix_x4(al[m2][0], al[m2][1], al[m2][2], al[m2][3], smem_u32(&S[idx + 512]));
                }
#pragma unroll
                for (int m2 = 0; m2 < 2; m2++)
#pragma unroll
                    for (int ni = 0; ni < 4; ni++) {
                        float* d = acc[mp * 2 + m2][ni];
                        mma16816(d[0], d[1], d[2], d[3],
                                 ah[m2][0], ah[m2][1], ah[m2][2], ah[m2][3], bh[ni][0], bh[ni][1]);
                        mma16816(d[0], d[1], d[2], d[3],
                                 al[m2][0], al[m2][1], al[m2][2], al[m2][3], bh[ni][0], bh[ni][1]);
                        mma16816(d[0], d[1], d[2], d[3],
                                 ah[m2][0], ah[m2][1], ah[m2][2], ah[m2][3], bl[ni][0], bl[ni][1]);
                    }
            }
        }
        cstage = (cstage == 2) ? 0 : cstage + 1;
    }

    const int crow0 = rowA0 + wm * 64;
    const int ccol0 = rowB0 + wn * 32;
#pragma unroll
    for (int mi = 0; mi < 4; mi++) {
#pragma unroll
        for (int ni = 0; ni < 4; ni++) {
            int r = crow0 + mi * 16 + (lane >> 2);
            int c = ccol0 + ni * 8 + (lane & 3) * 2;
            float b0 = bias[c], b1 = bias[c + 1];
            float* d = acc[mi][ni];
            *reinterpret_cast<float2*>(C + (size_t)r * OUTc + c) =
                make_float2(d[0] + b0, d[1] + b1);
            *reinterpret_cast<float2*>(C + (size_t)(r + 8) * OUTc + c) =
                make_float2(d[2] + b0, d[3] + b1);
        }
    }
}

// ---------------- LR@vs with 4-way K-split (unchanged) ----------------
__global__ void __launch_bounds__(256, 2)
gemm_lr1_kernel(const __half* __restrict__ Ah, const __half* __restrict__ Al,
                const __half* __restrict__ Bh, const __half* __restrict__ Bl) {
    constexpr int BK = 32;
    constexpr int KT = 32;               // 1024 / 32
    extern __shared__ uint4 Sd[];
    const int tid = threadIdx.x;
    const int rowA0 = blockIdx.y * 128;
    const int kz = blockIdx.z;
    const int kbase = kz * (Dc / 4);
    float* out = g_tmp4[kz];

    auto load_tile = [&](int stage, int kt) {
        const int k0 = kbase + kt * BK;
        const int so = stage * 2048;
#pragma unroll
        for (int i = tid; i < 512; i += 256) {
            int r = i >> 2, c = i & 3;
            int d = so + (r << 2) + (c ^ ((r >> 1) & 3));
            size_t srcA = (size_t)(rowA0 + r) * Dc + k0 + c * 8;
            cp_async16(smem_u32(&Sd[d]), Ah + srcA);
            cp_async16(smem_u32(&Sd[d + 512]), Al + srcA);
            size_t srcB = (size_t)r * Dc + k0 + c * 8;   // rowB0 = 0
            cp_async16(smem_u32(&Sd[d + 1024]), Bh + srcB);
            cp_async16(smem_u32(&Sd[d + 1536]), Bl + srcB);
        }
        cp_commit();
    };

    const int warp = tid >> 5, lane = tid & 31;
    const int wm = warp & 1;
    const int wn = warp >> 1;

    float acc[4][4][4];
#pragma unroll
    for (int i = 0; i < 4; i++)
#pragma unroll
        for (int j = 0; j < 4; j++)
#pragma unroll
            for (int k = 0; k < 4; k++) acc[i][j][k] = 0.f;

    load_tile(0, 0);
    load_tile(1, 1);

    int cstage = 0;
    for (int kt = 0; kt < KT; kt++) {
        if (kt >= KT - 1) cp_wait<0>(); else cp_wait<1>();
        __syncthreads();
        if (kt + 2 < KT) {
            int lstage = cstage == 0 ? 2 : cstage - 1;
            load_tile(lstage, kt + 2);
        }
        const int so = cstage * 2048;
#pragma unroll
        for (int ks = 0; ks < 2; ks++) {
            unsigned bh[4][2], bl[4][2];
#pragma unroll
            for (int nb = 0; nb < 2; nb++) {
                int n = wn * 32 + nb * 16 + (lane & 7) + ((lane >> 4) << 3);
                int kc = ks * 2 + ((lane >> 3) & 1);
                int idx = so + 1024 + (n << 2) + (kc ^ ((n >> 1) & 3));
                unsigned r0, r1, r2, r3;
                ldmatrix_x4(r0, r1, r2, r3, smem_u32(&Sd[idx]));
                bh[nb * 2][0] = r0;     bh[nb * 2][1] = r1;
                bh[nb * 2 + 1][0] = r2; bh[nb * 2 + 1][1] = r3;
                ldmatrix_x4(r0, r1, r2, r3, smem_u32(&Sd[idx + 512]));
                bl[nb * 2][0] = r0;     bl[nb * 2][1] = r1;
                bl[nb * 2 + 1][0] = r2; bl[nb * 2 + 1][1] = r3;
            }
#pragma unroll
            for (int mp = 0; mp < 2; mp++) {
                unsigned ah[2][4], al[2][4];
#pragma unroll
                for (int m2 = 0; m2 < 2; m2++) {
                    int mi = mp * 2 + m2;
                    int m = wm * 64 + mi * 16 + (lane & 15);
                    int kc = ks * 2 + (lane >> 4);
                    int idx = so + (m << 2) + (kc ^ ((m >> 1) & 3));
                    ldmatrix_x4(ah[m2][0], ah[m2][1], ah[m2][2], ah[m2][3], smem_u32(&Sd[idx]));
                    ldmatrix_x4(al[m2][0], al[m2][1], al[m2][2], al[m2][3], smem_u32(&Sd[idx + 512]));
                }
#pragma unroll
                for (int m2 = 0; m2 < 2; m2++)
#pragma unroll
                    for (int ni = 0; ni < 4; ni++) {
                        float* d = acc[mp * 2 + m2][ni];
                        mma16816(d[0], d[1], d[2], d[3],
                                 ah[m2][0], ah[m2][1], ah[m2][2], ah[m2][3], bh[ni][0], bh[ni][1]);
                        mma16816(d[0], d[1], d[2], d[3],
                                 al[m2][0], al[m2][1], al[m2][2], al[m2][3], bh[ni][0], bh[ni][1]);
                        mma16816(d[0], d[1], d[2], d[3],
                                 ah[m2][0], ah[m2][1], ah[m2][2], ah[m2][3], bl[ni][0], bl[ni][1]);
                    }
            }
        }
        cstage = (cstage == 2) ? 0 : cstage + 1;
    }

    const int crow0 = rowA0 + wm * 64;
    const int ccol0 = wn * 32;
#pragma unroll
    for (int mi = 0; mi < 4; mi++) {
#pragma unroll
        for (int ni = 0; ni < 4; ni++) {
            int r = crow0 + mi * 16 + (lane >> 2);
            int c = ccol0 + ni * 8 + (lane & 3) * 2;
            float* d = acc[mi][ni];
            *reinterpret_cast<float2*>(out + (size_t)r * RANKc + c) = make_float2(d[0], d[1]);
            *reinterpret_cast<float2*>(out + (size_t)(r + 8) * RANKc + c) = make_float2(d[2], d[3]);
        }
    }
}

// ---------------- launch ----------------
extern "C" void kernel_launch(void* const* d_in, const int* in_sizes, int n_in,
                              void* d_out, int out_size) {
    const float* x         = (const float*)d_in[0];
    const float* W         = (const float*)d_in[1];
    const float* bias      = (const float*)d_in[2];
    const float* vs        = (const float*)d_in[3];
    const float* u_t       = (const float*)d_in[4];
    const float* scale_vec = (const float*)d_in[5];
    const float* threshold = (const float*)d_in[6];
    const int*   rix       = (const int*)d_in[7];

    void *pXh, *pXl, *pLRh, *pLRl, *pWhh, *pWll, *pvsh, *pvsl, *puth, *putl, *ptmph, *ptmpl;
    cudaGetSymbolAddress(&pXh,  g_Xh);
    cudaGetSymbolAddress(&pXl,  g_Xl);
    cudaGetSymbolAddress(&pLRh, g_LRh);
    cudaGetSymbolAddress(&pLRl, g_LRl);
    cudaGetSymbolAddress(&pWhh, g_Whh);
    cudaGetSymbolAddress(&pWll, g_Wll);
    cudaGetSymbolAddress(&pvsh, g_vsh);
    cudaGetSymbolAddress(&pvsl, g_vsl);
    cudaGetSymbolAddress(&puth, g_uth);
    cudaGetSymbolAddress(&putl, g_utl);
    cudaGetSymbolAddress(&ptmph, g_tmph);
    cudaGetSymbolAddress(&ptmpl, g_tmpl);

    constexpr int SMEM_LR1 = 3 * 2048 * 16; // 96 KB
    cudaFuncSetAttribute(gemm_lr1_kernel, cudaFuncAttributeMaxDynamicSharedMemorySize, SMEM_LR1);
    cudaFuncSetAttribute(gemm_main_kernel, cudaFuncAttributeMaxDynamicSharedMemorySize, MAIN_SMEM);

    // [0] fused operand conversion (W split + vs/u_t transpose-split + maxbits reset)
    convert_all_kernel<<<2560, 256>>>(W, vs, u_t);
    // [1] absmax reduction
    reduce_max_kernel<<<1184, 256>>>(x, scale_vec, threshold);
    // [2] activation fp4-quant + fp16 split (occupancy-unlocked)
    quantize_kernel<<<MTOK, 256>>>(x, scale_vec, threshold, rix);
    // [3] tmp partials: LR @ vs, 4-way K-split
    {
        dim3 grid(1, MTOK / 128, 4);
        gemm_lr1_kernel<<<grid, 256, SMEM_LR1>>>(
            (const __half*)pLRh, (const __half*)pLRl,
            (const __half*)pvsh, (const __half*)pvsl);
    }
    // [4] reduce partials -> split-fp16 tmp
    sum_split_kernel<<<(MTOK * RANKc + 255) / 256, 256>>>();
    // [5] fused MAIN: out = Xq @ W^T + tmp @ u_t + bias  (K=4224, R8 config)
    gemm_main_kernel<<<2048, 256, MAIN_SMEM>>>(
        (const __half*)pXh, (const __half*)pXl,
        (const __half*)pWhh, (const __half*)pWll,
        (const __half*)ptmph, (const __half*)ptmpl,
        (const __half*)puth, (const __half*)putl,
        (float*)d_out, bias);
}

// round 13
// speedup vs baseline: 1.0933x; 1.0169x over previous
#include <cuda_runtime.h>
#include <cuda_fp16.h>
#include <cstdint>

#define DEV_INLINE __device__ __forceinline__

// ---------------- problem constants (fixed shapes) ----------------
constexpr int Bc = 4, Tc = 2048, Dc = 4096, OUTc = 4096, RANKc = 128, SELECTc = 128, GROUPc = 16;
constexpr int MTOK = Bc * Tc;         // 8192 token rows
constexpr int SPARSE_T = 204;         // int(2048 * (1 - 0.9))
constexpr float SCALE_CAP = 448.0f * 6.0f;
constexpr int KFUSE = Dc + RANKc;     // 4224

// ---------------- scratch (device globals) ----------------
__device__ __half  g_Xh [(size_t)MTOK * Dc];
__device__ __half  g_Xl [(size_t)MTOK * Dc];
__device__ __half  g_LRh[(size_t)MTOK * Dc];    // fp16-only LR input (low half dropped by design)
__device__ __half  g_Whh[(size_t)OUTc * Dc];
__device__ __half  g_Wll[(size_t)OUTc * Dc];
__device__ __half  g_vsh[(size_t)RANKc * Dc];   // vs^T [r][d]
__device__ __half  g_vsl[(size_t)RANKc * Dc];
__device__ __half  g_uth[(size_t)OUTc * RANKc]; // u_t^T [o][r]
__device__ __half  g_utl[(size_t)OUTc * RANKc];
__device__ __half  g_tmph[(size_t)MTOK * RANKc];
__device__ __half  g_tmpl[(size_t)MTOK * RANKc];
__device__ float   g_tmp4[4][(size_t)MTOK * RANKc]; // K-split partials
__device__ unsigned g_maxbits[2];

DEV_INLINE void split2(float v, __half& h, __half& l) {
    __half hh = __float2half(v);
    h = hh;
    l = __float2half(v - __half2float(hh));
}

// ---------------- fused operand conversion ----------------
__global__ void __launch_bounds__(256) convert_all_kernel(const float* __restrict__ W,
                                                          const float* __restrict__ vs,
                                                          const float* __restrict__ u_t) {
    if (blockIdx.x == 0 && threadIdx.x < 2) g_maxbits[threadIdx.x] = 0u;
    if (blockIdx.x < 2048) {
        const size_t base = (size_t)blockIdx.x * (OUTc * Dc / 2048);
        const size_t cnt = OUTc * Dc / 2048; // 8192 per block
        for (size_t k = threadIdx.x * 4; k < cnt; k += 1024) {
            float4 v4 = *reinterpret_cast<const float4*>(W + base + k);
            __half h0, l0, h1, l1, h2, l2, h3, l3;
            split2(v4.x, h0, l0); split2(v4.y, h1, l1);
            split2(v4.z, h2, l2); split2(v4.w, h3, l3);
            __half2 hh01 = __halves2half2(h0, h1), hh23 = __halves2half2(h2, h3);
            __half2 ll01 = __halves2half2(l0, l1), ll23 = __halves2half2(l2, l3);
            uint2 uh, ul;
            uh.x = *reinterpret_cast<unsigned*>(&hh01); uh.y = *reinterpret_cast<unsigned*>(&hh23);
            ul.x = *reinterpret_cast<unsigned*>(&ll01); ul.y = *reinterpret_cast<unsigned*>(&ll23);
            *reinterpret_cast<uint2*>(g_Whh + base + k) = uh;
            *reinterpret_cast<uint2*>(g_Wll + base + k) = ul;
        }
    } else {
        const int b = blockIdx.x - 2048;
        const int n = Dc * RANKc;
        const int stride = 512 * 256;
        for (int i = b * 256 + threadIdx.x; i < n; i += stride) {
            int d = i / RANKc, r = i - d * RANKc;
            __half h, l; split2(vs[i], h, l);
            g_vsh[(size_t)r * Dc + d] = h;
            g_vsl[(size_t)r * Dc + d] = l;
        }
        for (int i = b * 256 + threadIdx.x; i < n; i += stride) {
            int r = i / OUTc, o = i - r * OUTc;
            __half h, l; split2(u_t[i], h, l);
            g_uth[(size_t)o * RANKc + r] = h;
            g_utl[(size_t)o * RANKc + r] = l;
        }
    }
}

__global__ void reduce_max_kernel(const float* __restrict__ x,
                                  const float* __restrict__ scale_vec,
                                  const float* __restrict__ threshold) {
    const float thr = threshold[0];
    float mpre = 0.f, mdec = 0.f;
    const size_t n4 = (size_t)MTOK * Dc / 4;
    for (size_t i4 = (size_t)blockIdx.x * blockDim.x + threadIdx.x; i4 < n4;
         i4 += (size_t)gridDim.x * blockDim.x) {
        size_t i = i4 * 4;
        int d = (int)(i & (Dc - 1));
        int t = (int)((i >> 12) & (Tc - 1));
        float4 v = *reinterpret_cast<const float4*>(x + i);
        if (t < SPARSE_T) {
            mpre = fmaxf(mpre, fmaxf(fmaxf(fabsf(v.x), fabsf(v.y)), fmaxf(fabsf(v.z), fabsf(v.w))));
        } else {
            float4 sv = *reinterpret_cast<const float4*>(scale_vec + d);
            if (fabsf(v.x * sv.x) > thr) mdec = fmaxf(mdec, fabsf(v.x));
            if (fabsf(v.y * sv.y) > thr) mdec = fmaxf(mdec, fabsf(v.y));
            if (fabsf(v.z * sv.z) > thr) mdec = fmaxf(mdec, fabsf(v.z));
            if (fabsf(v.w * sv.w) > thr) mdec = fmaxf(mdec, fabsf(v.w));
        }
    }
#pragma unroll
    for (int o = 16; o; o >>= 1) {
        mpre = fmaxf(mpre, __shfl_xor_sync(0xffffffffu, mpre, o));
        mdec = fmaxf(mdec, __shfl_xor_sync(0xffffffffu, mdec, o));
    }
    __shared__ float spre[8], sdec[8];
    int w = threadIdx.x >> 5;
    if ((threadIdx.x & 31) == 0) { spre[w] = mpre; sdec[w] = mdec; }
    __syncthreads();
    if (threadIdx.x == 0) {
        float a = spre[0], b = sdec[0];
        for (int i = 1; i < (int)(blockDim.x >> 5); i++) {
            a = fmaxf(a, spre[i]); b = fmaxf(b, sdec[i]);
        }
        atomicMax(&g_maxbits[0], __float_as_uint(a));
        atomicMax(&g_maxbits[1], __float_as_uint(b));
    }
}

DEV_INLINE float fp4_mag(float a) {
    return a > 2.5f ? (a > 3.5f ? (a > 5.0f ? 6.0f : 4.0f) : 3.0f)
                    : (a > 1.25f ? (a > 1.75f ? 2.0f : 1.5f)
                                 : (a > 0.75f ? 1.0f : (a > 0.25f ? 0.5f : 0.0f)));
}

// One block per token. LR stored fp16-only (low half deleted — error budget).
__global__ void __launch_bounds__(256, 5) quantize_kernel(const float* __restrict__ x,
                                                          const float* __restrict__ scale_vec,
                                                          const float* __restrict__ threshold,
                                                          const int* __restrict__ rix) {
    __shared__ float sx[Dc];   // 16 KB

    const int tok = blockIdx.x;
    const int t = tok & (Tc - 1);
    const bool decode = (t >= SPARSE_T);
    const float thr = threshold[0];
    const float s = fmaxf(__uint_as_float(g_maxbits[decode ? 1 : 0]) / SCALE_CAP, 1e-12f);
    const float inv_s = 1.0f / s;
    const float* xrow = x + (size_t)tok * Dc;
    const int tid = threadIdx.x;

    __half* lrh = g_LRh + (size_t)tok * Dc;

    // phase 1: masked value -> sx; LR (fp16) -> global (vectorized)
#pragma unroll
    for (int it = 0; it < 4; it++) {
        int i = it * 1024 + tid * 4;
        float4 v = *reinterpret_cast<const float4*>(xrow + i);
        float4 masked, lr;
        if (decode) {
            float4 sv = *reinterpret_cast<const float4*>(scale_vec + i);
            bool m0 = fabsf(v.x * sv.x) > thr, m1 = fabsf(v.y * sv.y) > thr;
            bool m2 = fabsf(v.z * sv.z) > thr, m3 = fabsf(v.w * sv.w) > thr;
            masked = make_float4(m0 ? v.x : 0.f, m1 ? v.y : 0.f, m2 ? v.z : 0.f, m3 ? v.w : 0.f);
            lr     = make_float4(m0 ? 0.f : v.x, m1 ? 0.f : v.y, m2 ? 0.f : v.z, m3 ? 0.f : v.w);
        } else {
            masked = v; lr = make_float4(0.f, 0.f, 0.f, 0.f);
        }
        *reinterpret_cast<float4*>(sx + i) = masked;
        __half2 h01 = __floats2half2_rn(lr.x, lr.y);
        __half2 h23 = __floats2half2_rn(lr.z, lr.w);
        uint2 uh;
        uh.x = *reinterpret_cast<unsigned*>(&h01);
        uh.y = *reinterpret_cast<unsigned*>(&h23);
        *reinterpret_cast<uint2*>(lrh + i) = uh;
    }
    __syncthreads();

    // phase 2: fp4 quant in reordered space; indices straight from global.
    {
        int j0 = (tid < 8) ? tid * 16 : SELECTc + (tid - 8) * GROUPc;
        int ris[16];
#pragma unroll
        for (int c = 0; c < 4; c++)
            *reinterpret_cast<int4*>(ris + c * 4) =
                *reinterpret_cast<const int4*>(rix + j0 + c * 4);

        if (tid < 8) {
#pragma unroll
            for (int k = 0; k < 16; k++) {
                int ri = ris[k];
                float xr = sx[ri] * inv_s;
                sx[ri] = xr * s;
            }
        } else {
            float gmax = 0.f;
#pragma unroll
            for (int k = 0; k < GROUPc; k++) {
                float v = sx[ris[k]] * inv_s;
                gmax = fmaxf(gmax, fabsf(v));
            }
            float gs, inv_gs;
            if (gmax > 0.f) { gs = gmax / 6.0f; inv_gs = 6.0f / gmax; }
            else            { gs = 1.0f;       inv_gs = 1.0f; }
#pragma unroll
            for (int k = 0; k < GROUPc; k++) {
                int ri = ris[k];
                float v = sx[ri] * inv_s;
                float r = v * inv_gs;
                float q = fp4_mag(fabsf(r));
                q = (r < 0.f) ? -q : q;
                sx[ri] = (q * gs) * s;
            }
        }
    }
    __syncthreads();

    // phase 3: split-fp16 writeback (vectorized)
    __half* xh = g_Xh + (size_t)tok * Dc;
    __half* xl = g_Xl + (size_t)tok * Dc;
#pragma unroll
    for (int it = 0; it < 4; it++) {
        int i = it * 1024 + tid * 4;
        float4 v = *reinterpret_cast<const float4*>(sx + i);
        __half h0, l0, h1, l1, h2, l2, h3, l3;
        split2(v.x, h0, l0); split2(v.y, h1, l1);
        split2(v.z, h2, l2); split2(v.w, h3, l3);
        __half2 hh01 = __halves2half2(h0, h1), hh23 = __halves2half2(h2, h3);
        __half2 ll01 = __halves2half2(l0, l1), ll23 = __halves2half2(l2, l3);
        uint2 uh, ul;
        uh.x = *reinterpret_cast<unsigned*>(&hh01); uh.y = *reinterpret_cast<unsigned*>(&hh23);
        ul.x = *reinterpret_cast<unsigned*>(&ll01); ul.y = *reinterpret_cast<unsigned*>(&ll23);
        *reinterpret_cast<uint2*>(xh + i) = uh;
        *reinterpret_cast<uint2*>(xl + i) = ul;
    }
}

__global__ void sum_split_kernel() {
    int i = blockIdx.x * blockDim.x + threadIdx.x;
    if (i < MTOK * RANKc) {
        float s = g_tmp4[0][i] + g_tmp4[1][i] + g_tmp4[2][i] + g_tmp4[3][i];
        __half h, l; split2(s, h, l);
        g_tmph[i] = h; g_tmpl[i] = l;
    }
}

// ---------------- PTX helpers ----------------
DEV_INLINE unsigned smem_u32(const void* p) { return (unsigned)__cvta_generic_to_shared(p); }

DEV_INLINE void cp_async16(unsigned dst, const void* src) {
    asm volatile("cp.async.cg.shared.global [%0], [%1], 16;\n" :: "r"(dst), "l"(src));
}
DEV_INLINE void cp_commit() { asm volatile("cp.async.commit_group;\n"); }
template <int N> DEV_INLINE void cp_wait() { asm volatile("cp.async.wait_group %0;\n" :: "n"(N)); }

DEV_INLINE void ldmatrix_x4(unsigned& r0, unsigned& r1, unsigned& r2, unsigned& r3, unsigned addr) {
    asm volatile("ldmatrix.sync.aligned.m8n8.x4.shared.b16 {%0,%1,%2,%3}, [%4];\n"
                 : "=r"(r0), "=r"(r1), "=r"(r2), "=r"(r3) : "r"(addr));
}
DEV_INLINE void mma16816(float& d0, float& d1, float& d2, float& d3,
                         unsigned a0, unsigned a1, unsigned a2, unsigned a3,
                         unsigned b0, unsigned b1) {
    asm volatile("mma.sync.aligned.m16n8k16.row.col.f32.f16.f16.f32 "
                 "{%0,%1,%2,%3}, {%4,%5,%6,%7}, {%8,%9}, {%0,%1,%2,%3};\n"
                 : "+f"(d0), "+f"(d1), "+f"(d2), "+f"(d3)
                 : "r"(a0), "r"(a1), "r"(a2), "r"(a3), "r"(b0), "r"(b1));
}

// ================= fused main GEMM (R8-proven config, unchanged) =================
constexpr int MAIN_KT = KFUSE / 32;           // 132
constexpr int MAIN_SMEM = 3 * 2048 * 16;      // 96 KB

__global__ void __launch_bounds__(256, 2)
gemm_main_kernel(const __half* __restrict__ Ah, const __half* __restrict__ Al,
                 const __half* __restrict__ Bh, const __half* __restrict__ Bl,
                 const __half* __restrict__ Eah, const __half* __restrict__ Eal,
                 const __half* __restrict__ Ebh, const __half* __restrict__ Ebl,
                 float* __restrict__ C, const float* __restrict__ bias) {
    extern __shared__ uint4 S[];
    const int tid = threadIdx.x;

    // supertile raster: groups of 32 M-tiles x 8 N-tiles
    const int bid = blockIdx.x;
    const int gid = bid >> 8, wit = bid & 255;
    const int mt = (gid & 1) * 32 + (wit & 31);
    const int nt = (gid >> 1) * 8 + (wit >> 5);
    const int rowA0 = mt * 128;
    const int rowB0 = nt * 128;

    auto load_tile = [&](int stage, int kt) {
        const int so = stage * 2048;
#pragma unroll
        for (int i = tid; i < 512; i += 256) {
            int r = i >> 2, c = i & 3;
            int d = so + (r << 2) + (c ^ ((r >> 1) & 3));
            if (kt < Dc / 32) {
                size_t srcA = (size_t)(rowA0 + r) * Dc + kt * 32 + c * 8;
                cp_async16(smem_u32(&S[d]), Ah + srcA);
                cp_async16(smem_u32(&S[d + 512]), Al + srcA);
                size_t srcB = (size_t)(rowB0 + r) * Dc + kt * 32 + c * 8;
                cp_async16(smem_u32(&S[d + 1024]), Bh + srcB);
                cp_async16(smem_u32(&S[d + 1536]), Bl + srcB);
            } else {
                int k0 = (kt - Dc / 32) * 32;
                size_t srcA = (size_t)(rowA0 + r) * RANKc + k0 + c * 8;
                cp_async16(smem_u32(&S[d]), Eah + srcA);
                cp_async16(smem_u32(&S[d + 512]), Eal + srcA);
                size_t srcB = (size_t)(rowB0 + r) * RANKc + k0 + c * 8;
                cp_async16(smem_u32(&S[d + 1024]), Ebh + srcB);
                cp_async16(smem_u32(&S[d + 1536]), Ebl + srcB);
            }
        }
        cp_commit();
    };

    const int warp = tid >> 5, lane = tid & 31;
    const int wm = warp & 1;    // 2 warp-rows of 64
    const int wn = warp >> 1;   // 4 warp-cols of 32

    float acc[4][4][4];
#pragma unroll
    for (int i = 0; i < 4; i++)
#pragma unroll
        for (int j = 0; j < 4; j++)
#pragma unroll
            for (int k = 0; k < 4; k++) acc[i][j][k] = 0.f;

    load_tile(0, 0);
    load_tile(1, 1);

    int cstage = 0;
    for (int kt = 0; kt < MAIN_KT; kt++) {
        if (kt >= MAIN_KT - 1) cp_wait<0>(); else cp_wait<1>();
        __syncthreads();
        if (kt + 2 < MAIN_KT) {
            int lstage = cstage == 0 ? 2 : cstage - 1;
            load_tile(lstage, kt + 2);
        }
        const int so = cstage * 2048;
#pragma unroll
        for (int ks = 0; ks < 2; ks++) {
            unsigned bh[4][2], bl[4][2];
#pragma unroll
            for (int nb = 0; nb < 2; nb++) {
                int n = wn * 32 + nb * 16 + (lane & 7) + ((lane >> 4) << 3);
                int kc = ks * 2 + ((lane >> 3) & 1);
                int idx = so + 1024 + (n << 2) + (kc ^ ((n >> 1) & 3));
                unsigned r0, r1, r2, r3;
                ldmatrix_x4(r0, r1, r2, r3, smem_u32(&S[idx]));
                bh[nb * 2][0] = r0;     bh[nb * 2][1] = r1;
                bh[nb * 2 + 1][0] = r2; bh[nb * 2 + 1][1] = r3;
                ldmatrix_x4(r0, r1, r2, r3, smem_u32(&S[idx + 512]));
                bl[nb * 2][0] = r0;     bl[nb * 2][1] = r1;
                bl[nb * 2 + 1][0] = r2; bl[nb * 2 + 1][1] = r3;
            }
#pragma unroll
            for (int mp = 0; mp < 2; mp++) {
                unsigned ah[2][4], al[2][4];
#pragma unroll
                for (int m2 = 0; m2 < 2; m2++) {
                    int mi = mp * 2 + m2;
                    int m = wm * 64 + mi * 16 + (lane & 15);
                    int kc = ks * 2 + (lane >> 4);
                    int idx = so + (m << 2) + (kc ^ ((m >> 1) & 3));
                    ldmatrix_x4(ah[m2][0], ah[m2][1], ah[m2][2], ah[m2][3], smem_u32(&S[idx]));
                    ldmatrix_x4(al[m2][0], al[m2][1], al[m2][2], al[m2][3], smem_u32(&S[idx + 512]));
                }
#pragma unroll
                for (int m2 = 0; m2 < 2; m2++)
#pragma unroll
                    for (int ni = 0; ni < 4; ni++) {
                        float* d = acc[mp * 2 + m2][ni];
                        mma16816(d[0], d[1], d[2], d[3],
                                 ah[m2][0], ah[m2][1], ah[m2][2], ah[m2][3], bh[ni][0], bh[ni][1]);
                        mma16816(d[0], d[1], d[2], d[3],
                                 al[m2][0], al[m2][1], al[m2][2], al[m2][3], bh[ni][0], bh[ni][1]);
                        mma16816(d[0], d[1], d[2], d[3],
                                 ah[m2][0], ah[m2][1], ah[m2][2], ah[m2][3], bl[ni][0], bl[ni][1]);
                    }
            }
        }
        cstage = (cstage == 2) ? 0 : cstage + 1;
    }

    const int crow0 = rowA0 + wm * 64;
    const int ccol0 = rowB0 + wn * 32;
#pragma unroll
    for (int mi = 0; mi < 4; mi++) {
#pragma unroll
        for (int ni = 0; ni < 4; ni++) {
            int r = crow0 + mi * 16 + (lane >> 2);
            int c = ccol0 + ni * 8 + (lane & 3) * 2;
            float b0 = bias[c], b1 = bias[c + 1];
            float* d = acc[mi][ni];
            *reinterpret_cast<float2*>(C + (size_t)r * OUTc + c) =
                make_float2(d[0] + b0, d[1] + b1);
            *reinterpret_cast<float2*>(C + (size_t)(r + 8) * OUTc + c) =
                make_float2(d[2] + b0, d[3] + b1);
        }
    }
}

// ---------------- LR@vs with 4-way K-split: A fp16-only, B split (2 MMA terms) ----------------
// stage layout (uint4): A[512] Bh[512] Bl[512] = 1536/stage; 3 stages = 72 KB.
__global__ void __launch_bounds__(256, 2)
gemm_lr1_kernel(const __half* __restrict__ A,
                const __half* __restrict__ Bh, const __half* __restrict__ Bl) {
    constexpr int BK = 32;
    constexpr int KT = 32;               // 1024 / 32
    extern __shared__ uint4 Sd[];
    const int tid = threadIdx.x;
    const int rowA0 = blockIdx.y * 128;
    const int kz = blockIdx.z;
    const int kbase = kz * (Dc / 4);
    float* out = g_tmp4[kz];

    auto load_tile = [&](int stage, int kt) {
        const int k0 = kbase + kt * BK;
        const int so = stage * 1536;
#pragma unroll
        for (int i = tid; i < 512; i += 256) {
            int r = i >> 2, c = i & 3;
            int d = so + (r << 2) + (c ^ ((r >> 1) & 3));
            size_t srcA = (size_t)(rowA0 + r) * Dc + k0 + c * 8;
            cp_async16(smem_u32(&Sd[d]), A + srcA);
            size_t srcB = (size_t)r * Dc + k0 + c * 8;   // rowB0 = 0
            cp_async16(smem_u32(&Sd[d + 512]), Bh + srcB);
            cp_async16(smem_u32(&Sd[d + 1024]), Bl + srcB);
        }
        cp_commit();
    };

    const int warp = tid >> 5, lane = tid & 31;
    const int wm = warp & 1;
    const int wn = warp >> 1;

    float acc[4][4][4];
#pragma unroll
    for (int i = 0; i < 4; i++)
#pragma unroll
        for (int j = 0; j < 4; j++)
#pragma unroll
            for (int k = 0; k < 4; k++) acc[i][j][k] = 0.f;

    load_tile(0, 0);
    load_tile(1, 1);

    int cstage = 0;
    for (int kt = 0; kt < KT; kt++) {
        if (kt >= KT - 1) cp_wait<0>(); else cp_wait<1>();
        __syncthreads();
        if (kt + 2 < KT) {
            int lstage = cstage == 0 ? 2 : cstage - 1;
            load_tile(lstage, kt + 2);
        }
        const int so = cstage * 1536;
#pragma unroll
        for (int ks = 0; ks < 2; ks++) {
            unsigned bh[4][2], bl[4][2];
#pragma unroll
            for (int nb = 0; nb < 2; nb++) {
                int n = wn * 32 + nb * 16 + (lane & 7) + ((lane >> 4) << 3);
                int kc = ks * 2 + ((lane >> 3) & 1);
                int idx = so + 512 + (n << 2) + (kc ^ ((n >> 1) & 3));
                unsigned r0, r1, r2, r3;
                ldmatrix_x4(r0, r1, r2, r3, smem_u32(&Sd[idx]));
                bh[nb * 2][0] = r0;     bh[nb * 2][1] = r1;
                bh[nb * 2 + 1][0] = r2; bh[nb * 2 + 1][1] = r3;
                ldmatrix_x4(r0, r1, r2, r3, smem_u32(&Sd[idx + 512]));
                bl[nb * 2][0] = r0;     bl[nb * 2][1] = r1;
                bl[nb * 2 + 1][0] = r2; bl[nb * 2 + 1][1] = r3;
            }
#pragma unroll
            for (int mp = 0; mp < 2; mp++) {
                unsigned a[2][4];
#pragma unroll
                for (int m2 = 0; m2 < 2; m2++) {
                    int mi = mp * 2 + m2;
                    int m = wm * 64 + mi * 16 + (lane & 15);
                    int kc = ks * 2 + (lane >> 4);
                    int idx = so + (m << 2) + (kc ^ ((m >> 1) & 3));
                    ldmatrix_x4(a[m2][0], a[m2][1], a[m2][2], a[m2][3], smem_u32(&Sd[idx]));
                }
#pragma unroll
                for (int m2 = 0; m2 < 2; m2++)
#pragma unroll
                    for (int ni = 0; ni < 4; ni++) {
                        float* d = acc[mp * 2 + m2][ni];
                        mma16816(d[0], d[1], d[2], d[3],
                                 a[m2][0], a[m2][1], a[m2][2], a[m2][3], bh[ni][0], bh[ni][1]);
                        mma16816(d[0], d[1], d[2], d[3],
                                 a[m2][0], a[m2][1], a[m2][2], a[m2][3], bl[ni][0], bl[ni][1]);
                    }
            }
        }
        cstage = (cstage == 2) ? 0 : cstage + 1;
    }

    const int crow0 = rowA0 + wm * 64;
    const int ccol0 = wn * 32;
#pragma unroll
    for (int mi = 0; mi < 4; mi++) {
#pragma unroll
        for (int ni = 0; ni < 4; ni++) {
            int r = crow0 + mi * 16 + (lane >> 2);
            int c = ccol0 + ni * 8 + (lane & 3) * 2;
            float* d = acc[mi][ni];
            *reinterpret_cast<float2*>(out + (size_t)r * RANKc + c) = make_float2(d[0], d[1]);
            *reinterpret_cast<float2*>(out + (size_t)(r + 8) * RANKc + c) = make_float2(d[2], d[3]);
        }
    }
}

// ---------------- launch ----------------
extern "C" void kernel_launch(void* const* d_in, const int* in_sizes, int n_in,
                              void* d_out, int out_size) {
    const float* x         = (const float*)d_in[0];
    const float* W         = (const float*)d_in[1];
    const float* bias      = (const float*)d_in[2];
    const float* vs        = (const float*)d_in[3];
    const float* u_t       = (const float*)d_in[4];
    const float* scale_vec = (const float*)d_in[5];
    const float* threshold = (const float*)d_in[6];
    const int*   rix       = (const int*)d_in[7];

    void *pXh, *pXl, *pLRh, *pWhh, *pWll, *pvsh, *pvsl, *puth, *putl, *ptmph, *ptmpl;
    cudaGetSymbolAddress(&pXh,  g_Xh);
    cudaGetSymbolAddress(&pXl,  g_Xl);
    cudaGetSymbolAddress(&pLRh, g_LRh);
    cudaGetSymbolAddress(&pWhh, g_Whh);
    cudaGetSymbolAddress(&pWll, g_Wll);
    cudaGetSymbolAddress(&pvsh, g_vsh);
    cudaGetSymbolAddress(&pvsl, g_vsl);
    cudaGetSymbolAddress(&puth, g_uth);
    cudaGetSymbolAddress(&putl, g_utl);
    cudaGetSymbolAddress(&ptmph, g_tmph);
    cudaGetSymbolAddress(&ptmpl, g_tmpl);

    constexpr int SMEM_LR1 = 3 * 1536 * 16; // 72 KB
    cudaFuncSetAttribute(gemm_lr1_kernel, cudaFuncAttributeMaxDynamicSharedMemorySize, SMEM_LR1);
    cudaFuncSetAttribute(gemm_main_kernel, cudaFuncAttributeMaxDynamicSharedMemorySize, MAIN_SMEM);

    // [0] fused operand conversion (W split + vs/u_t transpose-split + maxbits reset)
    convert_all_kernel<<<2560, 256>>>(W, vs, u_t);
    // [1] absmax reduction
    reduce_max_kernel<<<1184, 256>>>(x, scale_vec, threshold);
    // [2] activation fp4-quant + fp16 split (LR fp16-only)
    quantize_kernel<<<MTOK, 256>>>(x, scale_vec, threshold, rix);
    // [3] tmp partials: LR @ vs, 4-way K-split (2-term exact-product)
    {
        dim3 grid(1, MTOK / 128, 4);
        gemm_lr1_kernel<<<grid, 256, SMEM_LR1>>>(
            (const __half*)pLRh,
            (const __half*)pvsh, (const __half*)pvsl);
    }
    // [4] reduce partials -> split-fp16 tmp
    sum_split_kernel<<<(MTOK * RANKc + 255) / 256, 256>>>();
    // [5] fused MAIN: out = Xq @ W^T + tmp @ u_t + bias  (K=4224, R8 config)
    gemm_main_kernel<<<2048, 256, MAIN_SMEM>>>(
        (const __half*)pXh, (const __half*)pXl,
        (const __half*)pWhh, (const __half*)pWll,
        (const __half*)ptmph, (const __half*)ptmpl,
        (const __half*)puth, (const __half*)putl,
        (float*)d_out, bias);
}

// round 14
// speedup vs baseline: 1.1022x; 1.0081x over previous
#include <cuda_runtime.h>
#include <cuda_fp16.h>
#include <cstdint>

#define DEV_INLINE __device__ __forceinline__

// ---------------- problem constants (fixed shapes) ----------------
constexpr int Bc = 4, Tc = 2048, Dc = 4096, OUTc = 4096, RANKc = 128, SELECTc = 128, GROUPc = 16;
constexpr int MTOK = Bc * Tc;         // 8192 token rows
constexpr int SPARSE_T = 204;         // int(2048 * (1 - 0.9))
constexpr float SCALE_CAP = 448.0f * 6.0f;
constexpr int KFUSE = Dc + RANKc;     // 4224

// ---------------- scratch (device globals) ----------------
__device__ __half  g_Xh [(size_t)MTOK * Dc];
__device__ __half  g_Xl [(size_t)MTOK * Dc];
__device__ __half  g_LRh[(size_t)MTOK * Dc];    // fp16-only LR input; prefill rows stay zero (zero-init)
__device__ __half  g_Whh[(size_t)OUTc * Dc];
__device__ __half  g_Wll[(size_t)OUTc * Dc];
__device__ __half  g_vsh[(size_t)RANKc * Dc];   // vs^T [r][d]
__device__ __half  g_vsl[(size_t)RANKc * Dc];
__device__ __half  g_uth[(size_t)OUTc * RANKc]; // u_t^T [o][r]
__device__ __half  g_utl[(size_t)OUTc * RANKc];
__device__ __half  g_tmph[(size_t)MTOK * RANKc];
__device__ __half  g_tmpl[(size_t)MTOK * RANKc];
__device__ float   g_tmp4[4][(size_t)MTOK * RANKc]; // K-split partials
__device__ unsigned g_maxbits[2];

DEV_INLINE void split2(float v, __half& h, __half& l) {
    __half hh = __float2half(v);
    h = hh;
    l = __float2half(v - __half2float(hh));
}

// ---------------- merged prep: operand conversion + absmax reduction ----------------
// blocks [0,2048): W split; [2048,2560): vs/u_t transpose-split;
// blocks [2560,3744): x absmax reduction (independent data -> overlapped).
// g_maxbits is reset by a cudaMemsetAsync BEFORE this launch.
__global__ void __launch_bounds__(256) prep_kernel(const float* __restrict__ W,
                                                   const float* __restrict__ vs,
                                                   const float* __restrict__ u_t,
                                                   const float* __restrict__ x,
                                                   const float* __restrict__ scale_vec,
                                                   const float* __restrict__ threshold) {
    if (blockIdx.x < 2048) {
        const size_t base = (size_t)blockIdx.x * (OUTc * Dc / 2048);
        const size_t cnt = OUTc * Dc / 2048; // 8192 per block
        for (size_t k = threadIdx.x * 4; k < cnt; k += 1024) {
            float4 v4 = *reinterpret_cast<const float4*>(W + base + k);
            __half h0, l0, h1, l1, h2, l2, h3, l3;
            split2(v4.x, h0, l0); split2(v4.y, h1, l1);
            split2(v4.z, h2, l2); split2(v4.w, h3, l3);
            __half2 hh01 = __halves2half2(h0, h1), hh23 = __halves2half2(h2, h3);
            __half2 ll01 = __halves2half2(l0, l1), ll23 = __halves2half2(l2, l3);
            uint2 uh, ul;
            uh.x = *reinterpret_cast<unsigned*>(&hh01); uh.y = *reinterpret_cast<unsigned*>(&hh23);
            ul.x = *reinterpret_cast<unsigned*>(&ll01); ul.y = *reinterpret_cast<unsigned*>(&ll23);
            *reinterpret_cast<uint2*>(g_Whh + base + k) = uh;
            *reinterpret_cast<uint2*>(g_Wll + base + k) = ul;
        }
    } else if (blockIdx.x < 2560) {
        const int b = blockIdx.x - 2048;
        const int n = Dc * RANKc;
        const int stride = 512 * 256;
        for (int i = b * 256 + threadIdx.x; i < n; i += stride) {
            int d = i / RANKc, r = i - d * RANKc;
            __half h, l; split2(vs[i], h, l);
            g_vsh[(size_t)r * Dc + d] = h;
            g_vsl[(size_t)r * Dc + d] = l;
        }
        for (int i = b * 256 + threadIdx.x; i < n; i += stride) {
            int r = i / OUTc, o = i - r * OUTc;
            __half h, l; split2(u_t[i], h, l);
            g_uth[(size_t)o * RANKc + r] = h;
            g_utl[(size_t)o * RANKc + r] = l;
        }
    } else {
        const int b = blockIdx.x - 2560;             // 0..1183
        const float thr = threshold[0];
        float mpre = 0.f, mdec = 0.f;
        const size_t n4 = (size_t)MTOK * Dc / 4;
        for (size_t i4 = (size_t)b * blockDim.x + threadIdx.x; i4 < n4;
             i4 += (size_t)1184 * blockDim.x) {
            size_t i = i4 * 4;
            int d = (int)(i & (Dc - 1));
            int t = (int)((i >> 12) & (Tc - 1));
            float4 v = *reinterpret_cast<const float4*>(x + i);
            if (t < SPARSE_T) {
                mpre = fmaxf(mpre, fmaxf(fmaxf(fabsf(v.x), fabsf(v.y)), fmaxf(fabsf(v.z), fabsf(v.w))));
            } else {
                float4 sv = *reinterpret_cast<const float4*>(scale_vec + d);
                if (fabsf(v.x * sv.x) > thr) mdec = fmaxf(mdec, fabsf(v.x));
                if (fabsf(v.y * sv.y) > thr) mdec = fmaxf(mdec, fabsf(v.y));
                if (fabsf(v.z * sv.z) > thr) mdec = fmaxf(mdec, fabsf(v.z));
                if (fabsf(v.w * sv.w) > thr) mdec = fmaxf(mdec, fabsf(v.w));
            }
        }
#pragma unroll
        for (int o = 16; o; o >>= 1) {
            mpre = fmaxf(mpre, __shfl_xor_sync(0xffffffffu, mpre, o));
            mdec = fmaxf(mdec, __shfl_xor_sync(0xffffffffu, mdec, o));
        }
        __shared__ float spre[8], sdec[8];
        int w = threadIdx.x >> 5;
        if ((threadIdx.x & 31) == 0) { spre[w] = mpre; sdec[w] = mdec; }
        __syncthreads();
        if (threadIdx.x == 0) {
            float a = spre[0], bb = sdec[0];
            for (int i = 1; i < 8; i++) { a = fmaxf(a, spre[i]); bb = fmaxf(bb, sdec[i]); }
            atomicMax(&g_maxbits[0], __float_as_uint(a));
            atomicMax(&g_maxbits[1], __float_as_uint(bb));
        }
    }
}

DEV_INLINE float fp4_mag(float a) {
    return a > 2.5f ? (a > 3.5f ? (a > 5.0f ? 6.0f : 4.0f) : 3.0f)
                    : (a > 1.25f ? (a > 1.75f ? 2.0f : 1.5f)
                                 : (a > 0.75f ? 1.0f : (a > 0.25f ? 0.5f : 0.0f)));
}

// One block per token. LR fp16-only; prefill rows skip the LR store entirely
// (their LR is identically zero and device globals are zero-initialized).
__global__ void __launch_bounds__(256, 5) quantize_kernel(const float* __restrict__ x,
                                                          const float* __restrict__ scale_vec,
                                                          const float* __restrict__ threshold,
                                                          const int* __restrict__ rix) {
    __shared__ float sx[Dc];   // 16 KB

    const int tok = blockIdx.x;
    const int t = tok & (Tc - 1);
    const bool decode = (t >= SPARSE_T);
    const float thr = threshold[0];
    const float s = fmaxf(__uint_as_float(g_maxbits[decode ? 1 : 0]) / SCALE_CAP, 1e-12f);
    const float inv_s = 1.0f / s;
    const float* xrow = x + (size_t)tok * Dc;
    const int tid = threadIdx.x;

    __half* lrh = g_LRh + (size_t)tok * Dc;

    // phase 1: masked value -> sx; LR (fp16) -> global (decode rows only)
#pragma unroll
    for (int it = 0; it < 4; it++) {
        int i = it * 1024 + tid * 4;
        float4 v = *reinterpret_cast<const float4*>(xrow + i);
        if (decode) {
            float4 sv = *reinterpret_cast<const float4*>(scale_vec + i);
            bool m0 = fabsf(v.x * sv.x) > thr, m1 = fabsf(v.y * sv.y) > thr;
            bool m2 = fabsf(v.z * sv.z) > thr, m3 = fabsf(v.w * sv.w) > thr;
            float4 masked = make_float4(m0 ? v.x : 0.f, m1 ? v.y : 0.f, m2 ? v.z : 0.f, m3 ? v.w : 0.f);
            float4 lr     = make_float4(m0 ? 0.f : v.x, m1 ? 0.f : v.y, m2 ? 0.f : v.z, m3 ? 0.f : v.w);
            *reinterpret_cast<float4*>(sx + i) = masked;
            __half2 h01 = __floats2half2_rn(lr.x, lr.y);
            __half2 h23 = __floats2half2_rn(lr.z, lr.w);
            uint2 uh;
            uh.x = *reinterpret_cast<unsigned*>(&h01);
            uh.y = *reinterpret_cast<unsigned*>(&h23);
            *reinterpret_cast<uint2*>(lrh + i) = uh;
        } else {
            *reinterpret_cast<float4*>(sx + i) = v;
        }
    }
    __syncthreads();

    // phase 2: fp4 quant in reordered space; indices straight from global.
    {
        int j0 = (tid < 8) ? tid * 16 : SELECTc + (tid - 8) * GROUPc;
        int ris[16];
#pragma unroll
        for (int c = 0; c < 4; c++)
            *reinterpret_cast<int4*>(ris + c * 4) =
                *reinterpret_cast<const int4*>(rix + j0 + c * 4);

        if (tid < 8) {
#pragma unroll
            for (int k = 0; k < 16; k++) {
                int ri = ris[k];
                float xr = sx[ri] * inv_s;
                sx[ri] = xr * s;
            }
        } else {
            float gmax = 0.f;
#pragma unroll
            for (int k = 0; k < GROUPc; k++) {
                float v = sx[ris[k]] * inv_s;
                gmax = fmaxf(gmax, fabsf(v));
            }
            float gs, inv_gs;
            if (gmax > 0.f) { gs = gmax / 6.0f; inv_gs = 6.0f / gmax; }
            else            { gs = 1.0f;       inv_gs = 1.0f; }
#pragma unroll
            for (int k = 0; k < GROUPc; k++) {
                int ri = ris[k];
                float v = sx[ri] * inv_s;
                float r = v * inv_gs;
                float q = fp4_mag(fabsf(r));
                q = (r < 0.f) ? -q : q;
                sx[ri] = (q * gs) * s;
            }
        }
    }
    __syncthreads();

    // phase 3: split-fp16 writeback (vectorized)
    __half* xh = g_Xh + (size_t)tok * Dc;
    __half* xl = g_Xl + (size_t)tok * Dc;
#pragma unroll
    for (int it = 0; it < 4; it++) {
        int i = it * 1024 + tid * 4;
        float4 v = *reinterpret_cast<const float4*>(sx + i);
        __half h0, l0, h1, l1, h2, l2, h3, l3;
        split2(v.x, h0, l0); split2(v.y, h1, l1);
        split2(v.z, h2, l2); split2(v.w, h3, l3);
        __half2 hh01 = __halves2half2(h0, h1), hh23 = __halves2half2(h2, h3);
        __half2 ll01 = __halves2half2(l0, l1), ll23 = __halves2half2(l2, l3);
        uint2 uh, ul;
        uh.x = *reinterpret_cast<unsigned*>(&hh01); uh.y = *reinterpret_cast<unsigned*>(&hh23);
        ul.x = *reinterpret_cast<unsigned*>(&ll01); ul.y = *reinterpret_cast<unsigned*>(&ll23);
        *reinterpret_cast<uint2*>(xh + i) = uh;
        *reinterpret_cast<uint2*>(xl + i) = ul;
    }
}

__global__ void sum_split_kernel() {
    int i = blockIdx.x * blockDim.x + threadIdx.x;
    if (i < MTOK * RANKc) {
        float s = g_tmp4[0][i] + g_tmp4[1][i] + g_tmp4[2][i] + g_tmp4[3][i];
        __half h, l; split2(s, h, l);
        g_tmph[i] = h; g_tmpl[i] = l;
    }
}

// ---------------- PTX helpers ----------------
DEV_INLINE unsigned smem_u32(const void* p) { return (unsigned)__cvta_generic_to_shared(p); }

DEV_INLINE void cp_async16(unsigned dst, const void* src) {
    asm volatile("cp.async.cg.shared.global [%0], [%1], 16;\n" :: "r"(dst), "l"(src));
}
DEV_INLINE void cp_commit() { asm volatile("cp.async.commit_group;\n"); }
template <int N> DEV_INLINE void cp_wait() { asm volatile("cp.async.wait_group %0;\n" :: "n"(N)); }

DEV_INLINE void ldmatrix_x4(unsigned& r0, unsigned& r1, unsigned& r2, unsigned& r3, unsigned addr) {
    asm volatile("ldmatrix.sync.aligned.m8n8.x4.shared.b16 {%0,%1,%2,%3}, [%4];\n"
                 : "=r"(r0), "=r"(r1), "=r"(r2), "=r"(r3) : "r"(addr));
}
DEV_INLINE void mma16816(float& d0, float& d1, float& d2, float& d3,
                         unsigned a0, unsigned a1, unsigned a2, unsigned a3,
                         unsigned b0, unsigned b1) {
    asm volatile("mma.sync.aligned.m16n8k16.row.col.f32.f16.f16.f32 "
                 "{%0,%1,%2,%3}, {%4,%5,%6,%7}, {%8,%9}, {%0,%1,%2,%3};\n"
                 : "+f"(d0), "+f"(d1), "+f"(d2), "+f"(d3)
                 : "r"(a0), "r"(a1), "r"(a2), "r"(a3), "r"(b0), "r"(b1));
}

// ================= fused main GEMM (R8-proven config, unchanged) =================
constexpr int MAIN_KT = KFUSE / 32;           // 132
constexpr int MAIN_SMEM = 3 * 2048 * 16;      // 96 KB

__global__ void __launch_bounds__(256, 2)
gemm_main_kernel(const __half* __restrict__ Ah, const __half* __restrict__ Al,
                 const __half* __restrict__ Bh, const __half* __restrict__ Bl,
                 const __half* __restrict__ Eah, const __half* __restrict__ Eal,
                 const __half* __restrict__ Ebh, const __half* __restrict__ Ebl,
                 float* __restrict__ C, const float* __restrict__ bias) {
    extern __shared__ uint4 S[];
    const int tid = threadIdx.x;

    // supertile raster: groups of 32 M-tiles x 8 N-tiles
    const int bid = blockIdx.x;
    const int gid = bid >> 8, wit = bid & 255;
    const int mt = (gid & 1) * 32 + (wit & 31);
    const int nt = (gid >> 1) * 8 + (wit >> 5);
    const int rowA0 = mt * 128;
    const int rowB0 = nt * 128;

    auto load_tile = [&](int stage, int kt) {
        const int so = stage * 2048;
#pragma unroll
        for (int i = tid; i < 512; i += 256) {
            int r = i >> 2, c = i & 3;
            int d = so + (r << 2) + (c ^ ((r >> 1) & 3));
            if (kt < Dc / 32) {
                size_t srcA = (size_t)(rowA0 + r) * Dc + kt * 32 + c * 8;
                cp_async16(smem_u32(&S[d]), Ah + srcA);
                cp_async16(smem_u32(&S[d + 512]), Al + srcA);
                size_t srcB = (size_t)(rowB0 + r) * Dc + kt * 32 + c * 8;
                cp_async16(smem_u32(&S[d + 1024]), Bh + srcB);
                cp_async16(smem_u32(&S[d + 1536]), Bl + srcB);
            } else {
                int k0 = (kt - Dc / 32) * 32;
                size_t srcA = (size_t)(rowA0 + r) * RANKc + k0 + c * 8;
                cp_async16(smem_u32(&S[d]), Eah + srcA);
                cp_async16(smem_u32(&S[d + 512]), Eal + srcA);
                size_t srcB = (size_t)(rowB0 + r) * RANKc + k0 + c * 8;
                cp_async16(smem_u32(&S[d + 1024]), Ebh + srcB);
                cp_async16(smem_u32(&S[d + 1536]), Ebl + srcB);
            }
        }
        cp_commit();
    };

    const int warp = tid >> 5, lane = tid & 31;
    const int wm = warp & 1;    // 2 warp-rows of 64
    const int wn = warp >> 1;   // 4 warp-cols of 32

    float acc[4][4][4];
#pragma unroll
    for (int i = 0; i < 4; i++)
#pragma unroll
        for (int j = 0; j < 4; j++)
#pragma unroll
            for (int k = 0; k < 4; k++) acc[i][j][k] = 0.f;

    load_tile(0, 0);
    load_tile(1, 1);

    int cstage = 0;
    for (int kt = 0; kt < MAIN_KT; kt++) {
        if (kt >= MAIN_KT - 1) cp_wait<0>(); else cp_wait<1>();
        __syncthreads();
        if (kt + 2 < MAIN_KT) {
            int lstage = cstage == 0 ? 2 : cstage - 1;
            load_tile(lstage, kt + 2);
        }
        const int so = cstage * 2048;
#pragma unroll
        for (int ks = 0; ks < 2; ks++) {
            unsigned bh[4][2], bl[4][2];
#pragma unroll
            for (int nb = 0; nb < 2; nb++) {
                int n = wn * 32 + nb * 16 + (lane & 7) + ((lane >> 4) << 3);
                int kc = ks * 2 + ((lane >> 3) & 1);
                int idx = so + 1024 + (n << 2) + (kc ^ ((n >> 1) & 3));
                unsigned r0, r1, r2, r3;
                ldmatrix_x4(r0, r1, r2, r3, smem_u32(&S[idx]));
                bh[nb * 2][0] = r0;     bh[nb * 2][1] = r1;
                bh[nb * 2 + 1][0] = r2; bh[nb * 2 + 1][1] = r3;
                ldmatrix_x4(r0, r1, r2, r3, smem_u32(&S[idx + 512]));
                bl[nb * 2][0] = r0;     bl[nb * 2][1] = r1;
                bl[nb * 2 + 1][0] = r2; bl[nb * 2 + 1][1] = r3;
            }
#pragma unroll
            for (int mp = 0; mp < 2; mp++) {
                unsigned ah[2][4], al[2][4];
#pragma unroll
                for (int m2 = 0; m2 < 2; m2++) {
                    int mi = mp * 2 + m2;
                    int m = wm * 64 + mi * 16 + (lane & 15);
                    int kc = ks * 2 + (lane >> 4);
                    int idx = so + (m << 2) + (kc ^ ((m >> 1) & 3));
                    ldmatrix_x4(ah[m2][0], ah[m2][1], ah[m2][2], ah[m2][3], smem_u32(&S[idx]));
                    ldmatrix_x4(al[m2][0], al[m2][1], al[m2][2], al[m2][3], smem_u32(&S[idx + 512]));
                }
#pragma unroll
                for (int m2 = 0; m2 < 2; m2++)
#pragma unroll
                    for (int ni = 0; ni < 4; ni++) {
                        float* d = acc[mp * 2 + m2][ni];
                        mma16816(d[0], d[1], d[2], d[3],
                                 ah[m2][0], ah[m2][1], ah[m2][2], ah[m2][3], bh[ni][0], bh[ni][1]);
                        mma16816(d[0], d[1], d[2], d[3],
                                 al[m2][0], al[m2][1], al[m2][2], al[m2][3], bh[ni][0], bh[ni][1]);
                        mma16816(d[0], d[1], d[2], d[3],
                                 ah[m2][0], ah[m2][1], ah[m2][2], ah[m2][3], bl[ni][0], bl[ni][1]);
                    }
            }
        }
        cstage = (cstage == 2) ? 0 : cstage + 1;
    }

    const int crow0 = rowA0 + wm * 64;
    const int ccol0 = rowB0 + wn * 32;
#pragma unroll
    for (int mi = 0; mi < 4; mi++) {
#pragma unroll
        for (int ni = 0; ni < 4; ni++) {
            int r = crow0 + mi * 16 + (lane >> 2);
            int c = ccol0 + ni * 8 + (lane & 3) * 2;
            float b0 = bias[c], b1 = bias[c + 1];
            float* d = acc[mi][ni];
            *reinterpret_cast<float2*>(C + (size_t)r * OUTc + c) =
                make_float2(d[0] + b0, d[1] + b1);
            *reinterpret_cast<float2*>(C + (size_t)(r + 8) * OUTc + c) =
                make_float2(d[2] + b0, d[3] + b1);
        }
    }
}

// ---------------- LR@vs with 4-way K-split: A fp16-only, B split (2 MMA terms) ----------------
__global__ void __launch_bounds__(256, 2)
gemm_lr1_kernel(const __half* __restrict__ A,
                const __half* __restrict__ Bh, const __half* __restrict__ Bl) {
    constexpr int BK = 32;
    constexpr int KT = 32;               // 1024 / 32
    extern __shared__ uint4 Sd[];
    const int tid = threadIdx.x;
    const int rowA0 = blockIdx.y * 128;
    const int kz = blockIdx.z;
    const int kbase = kz * (Dc / 4);
    float* out = g_tmp4[kz];

    auto load_tile = [&](int stage, int kt) {
        const int k0 = kbase + kt * BK;
        const int so = stage * 1536;
#pragma unroll
        for (int i = tid; i < 512; i += 256) {
            int r = i >> 2, c = i & 3;
            int d = so + (r << 2) + (c ^ ((r >> 1) & 3));
            size_t srcA = (size_t)(rowA0 + r) * Dc + k0 + c * 8;
            cp_async16(smem_u32(&Sd[d]), A + srcA);
            size_t srcB = (size_t)r * Dc + k0 + c * 8;   // rowB0 = 0
            cp_async16(smem_u32(&Sd[d + 512]), Bh + srcB);
            cp_async16(smem_u32(&Sd[d + 1024]), Bl + srcB);
        }
        cp_commit();
    };

    const int warp = tid >> 5, lane = tid & 31;
    const int wm = warp & 1;
    const int wn = warp >> 1;

    float acc[4][4][4];
#pragma unroll
    for (int i = 0; i < 4; i++)
#pragma unroll
        for (int j = 0; j < 4; j++)
#pragma unroll
            for (int k = 0; k < 4; k++) acc[i][j][k] = 0.f;

    load_tile(0, 0);
    load_tile(1, 1);

    int cstage = 0;
    for (int kt = 0; kt < KT; kt++) {
        if (kt >= KT - 1) cp_wait<0>(); else cp_wait<1>();
        __syncthreads();
        if (kt + 2 < KT) {
            int lstage = cstage == 0 ? 2 : cstage - 1;
            load_tile(lstage, kt + 2);
        }
        const int so = cstage * 1536;
#pragma unroll
        for (int ks = 0; ks < 2; ks++) {
            unsigned bh[4][2], bl[4][2];
#pragma unroll
            for (int nb = 0; nb < 2; nb++) {
                int n = wn * 32 + nb * 16 + (lane & 7) + ((lane >> 4) << 3);
                int kc = ks * 2 + ((lane >> 3) & 1);
                int idx = so + 512 + (n << 2) + (kc ^ ((n >> 1) & 3));
                unsigned r0, r1, r2, r3;
                ldmatrix_x4(r0, r1, r2, r3, smem_u32(&Sd[idx]));
                bh[nb * 2][0] = r0;     bh[nb * 2][1] = r1;
                bh[nb * 2 + 1][0] = r2; bh[nb * 2 + 1][1] = r3;
                ldmatrix_x4(r0, r1, r2, r3, smem_u32(&Sd[idx + 512]));
                bl[nb * 2][0] = r0;     bl[nb * 2][1] = r1;
                bl[nb * 2 + 1][0] = r2; bl[nb * 2 + 1][1] = r3;
            }
#pragma unroll
            for (int mp = 0; mp < 2; mp++) {
                unsigned a[2][4];
#pragma unroll
                for (int m2 = 0; m2 < 2; m2++) {
                    int mi = mp * 2 + m2;
                    int m = wm * 64 + mi * 16 + (lane & 15);
                    int kc = ks * 2 + (lane >> 4);
                    int idx = so + (m << 2) + (kc ^ ((m >> 1) & 3));
                    ldmatrix_x4(a[m2][0], a[m2][1], a[m2][2], a[m2][3], smem_u32(&Sd[idx]));
                }
#pragma unroll
                for (int m2 = 0; m2 < 2; m2++)
#pragma unroll
                    for (int ni = 0; ni < 4; ni++) {
                        float* d = acc[mp * 2 + m2][ni];
                        mma16816(d[0], d[1], d[2], d[3],
                                 a[m2][0], a[m2][1], a[m2][2], a[m2][3], bh[ni][0], bh[ni][1]);
                        mma16816(d[0], d[1], d[2], d[3],
                                 a[m2][0], a[m2][1], a[m2][2], a[m2][3], bl[ni][0], bl[ni][1]);
                    }
            }
        }
        cstage = (cstage == 2) ? 0 : cstage + 1;
    }

    const int crow0 = rowA0 + wm * 64;
    const int ccol0 = wn * 32;
#pragma unroll
    for (int mi = 0; mi < 4; mi++) {
#pragma unroll
        for (int ni = 0; ni < 4; ni++) {
            int r = crow0 + mi * 16 + (lane >> 2);
            int c = ccol0 + ni * 8 + (lane & 3) * 2;
            float* d = acc[mi][ni];
            *reinterpret_cast<float2*>(out + (size_t)r * RANKc + c) = make_float2(d[0], d[1]);
            *reinterpret_cast<float2*>(out + (size_t)(r + 8) * RANKc + c) = make_float2(d[2], d[3]);
        }
    }
}

// ---------------- launch ----------------
extern "C" void kernel_launch(void* const* d_in, const int* in_sizes, int n_in,
                              void* d_out, int out_size) {
    const float* x         = (const float*)d_in[0];
    const float* W         = (const float*)d_in[1];
    const float* bias      = (const float*)d_in[2];
    const float* vs        = (const float*)d_in[3];
    const float* u_t       = (const float*)d_in[4];
    const float* scale_vec = (const float*)d_in[5];
    const float* threshold = (const float*)d_in[6];
    const int*   rix       = (const int*)d_in[7];

    void *pXh, *pXl, *pLRh, *pWhh, *pWll, *pvsh, *pvsl, *puth, *putl, *ptmph, *ptmpl, *pmax;
    cudaGetSymbolAddress(&pXh,  g_Xh);
    cudaGetSymbolAddress(&pXl,  g_Xl);
    cudaGetSymbolAddress(&pLRh, g_LRh);
    cudaGetSymbolAddress(&pWhh, g_Whh);
    cudaGetSymbolAddress(&pWll, g_Wll);
    cudaGetSymbolAddress(&pvsh, g_vsh);
    cudaGetSymbolAddress(&pvsl, g_vsl);
    cudaGetSymbolAddress(&puth, g_uth);
    cudaGetSymbolAddress(&putl, g_utl);
    cudaGetSymbolAddress(&ptmph, g_tmph);
    cudaGetSymbolAddress(&ptmpl, g_tmpl);
    cudaGetSymbolAddress(&pmax, g_maxbits);

    constexpr int SMEM_LR1 = 3 * 1536 * 16; // 72 KB
    cudaFuncSetAttribute(gemm_lr1_kernel, cudaFuncAttributeMaxDynamicSharedMemorySize, SMEM_LR1);
    cudaFuncSetAttribute(gemm_main_kernel, cudaFuncAttributeMaxDynamicSharedMemorySize, MAIN_SMEM);

    // [0] reset absmax accumulators (graph memset node)
    cudaMemsetAsync(pmax, 0, 2 * sizeof(unsigned));
    // [1] merged prep: W/vs/u_t conversion overlapped with x absmax reduction
    prep_kernel<<<3744, 256>>>(W, vs, u_t, x, scale_vec, threshold);
    // [2] activation fp4-quant + fp16 split (LR fp16-only, prefill LR stores skipped)
    quantize_kernel<<<MTOK, 256>>>(x, scale_vec, threshold, rix);
    // [3] tmp partials: LR @ vs, 4-way K-split (2-term exact-product)
    {
        dim3 grid(1, MTOK / 128, 4);
        gemm_lr1_kernel<<<grid, 256, SMEM_LR1>>>(
            (const __half*)pLRh,
            (const __half*)pvsh, (const __half*)pvsl);
    }
    // [4] reduce partials -> split-fp16 tmp
    sum_split_kernel<<<(MTOK * RANKc + 255) / 256, 256>>>();
    // [5] fused MAIN: out = Xq @ W^T + tmp @ u_t + bias  (K=4224, R8 config)
    gemm_main_kernel<<<2048, 256, MAIN_SMEM>>>(
        (const __half*)pXh, (const __half*)pXl,
        (const __half*)pWhh, (const __half*)pWll,
        (const __half*)ptmph, (const __half*)ptmpl,
        (const __half*)puth, (const __half*)putl,
        (float*)d_out, bias);
}

// round 15
// speedup vs baseline: 1.1037x; 1.0014x over previous
#include <cuda_runtime.h>
#include <cuda_fp16.h>
#include <cstdint>

#define DEV_INLINE __device__ __forceinline__

// ---------------- problem constants (fixed shapes) ----------------
constexpr int Bc = 4, Tc = 2048, Dc = 4096, OUTc = 4096, RANKc = 128, SELECTc = 128, GROUPc = 16;
constexpr int MTOK = Bc * Tc;         // 8192 token rows
constexpr int SPARSE_T = 204;         // int(2048 * (1 - 0.9))
constexpr float SCALE_CAP = 448.0f * 6.0f;
constexpr int KFUSE = Dc + RANKc;     // 4224

// ---------------- scratch (device globals) ----------------
__device__ __half  g_Xh [(size_t)MTOK * Dc];
__device__ __half  g_Xl [(size_t)MTOK * Dc];
__device__ __half  g_LRh[(size_t)MTOK * Dc];    // fp16-only LR input; prefill rows stay zero (zero-init)
__device__ __half  g_Whh[(size_t)OUTc * Dc];
__device__ __half  g_Wll[(size_t)OUTc * Dc];
__device__ __half  g_vsh[(size_t)RANKc * Dc];   // vs^T [r][d]
__device__ __half  g_vsl[(size_t)RANKc * Dc];
__device__ __half  g_uth[(size_t)OUTc * RANKc]; // u_t^T [o][r]
__device__ __half  g_utl[(size_t)OUTc * RANKc];
__device__ __half  g_tmph[(size_t)MTOK * RANKc];
__device__ __half  g_tmpl[(size_t)MTOK * RANKc];
__device__ float   g_tmp4[4][(size_t)MTOK * RANKc]; // K-split partials
__device__ unsigned g_maxbits[2];

DEV_INLINE void split2(float v, __half& h, __half& l) {
    __half hh = __float2half(v);
    h = hh;
    l = __float2half(v - __half2float(hh));
}

// Packed split: 4 floats -> (hi fp16 x4, lo fp16 x4) using f16x2 conversions.
// Rounding identical to split2 (rn both directions) -> bit-identical results.
DEV_INLINE void split4(float4 v, uint2& uh, uint2& ul) {
    __half2 h01 = __floats2half2_rn(v.x, v.y);
    __half2 h23 = __floats2half2_rn(v.z, v.w);
    float2 f01 = __half22float2(h01);
    float2 f23 = __half22float2(h23);
    __half2 l01 = __floats2half2_rn(v.x - f01.x, v.y - f01.y);
    __half2 l23 = __floats2half2_rn(v.z - f23.x, v.w - f23.y);
    uh.x = *reinterpret_cast<unsigned*>(&h01);
    uh.y = *reinterpret_cast<unsigned*>(&h23);
    ul.x = *reinterpret_cast<unsigned*>(&l01);
    ul.y = *reinterpret_cast<unsigned*>(&l23);
}

// ---------------- merged prep: operand conversion + absmax reduction ----------------
// blocks [0,2048): W split; [2048,2560): vs/u_t transpose-split;
// blocks [2560,3744): x absmax reduction. g_maxbits reset via cudaMemsetAsync.
__global__ void __launch_bounds__(256) prep_kernel(const float* __restrict__ W,
                                                   const float* __restrict__ vs,
                                                   const float* __restrict__ u_t,
                                                   const float* __restrict__ x,
                                                   const float* __restrict__ scale_vec,
                                                   const float* __restrict__ threshold) {
    if (blockIdx.x < 2048) {
        const size_t base = (size_t)blockIdx.x * (OUTc * Dc / 2048);
        const size_t cnt = OUTc * Dc / 2048; // 8192 per block
        for (size_t k = threadIdx.x * 4; k < cnt; k += 1024) {
            float4 v4 = *reinterpret_cast<const float4*>(W + base + k);
            uint2 uh, ul;
            split4(v4, uh, ul);
            *reinterpret_cast<uint2*>(g_Whh + base + k) = uh;
            *reinterpret_cast<uint2*>(g_Wll + base + k) = ul;
        }
    } else if (blockIdx.x < 2560) {
        const int b = blockIdx.x - 2048;
        const int n = Dc * RANKc;
        const int stride = 512 * 256;
        for (int i = b * 256 + threadIdx.x; i < n; i += stride) {
            int d = i / RANKc, r = i - d * RANKc;
            __half h, l; split2(vs[i], h, l);
            g_vsh[(size_t)r * Dc + d] = h;
            g_vsl[(size_t)r * Dc + d] = l;
        }
        for (int i = b * 256 + threadIdx.x; i < n; i += stride) {
            int r = i / OUTc, o = i - r * OUTc;
            __half h, l; split2(u_t[i], h, l);
            g_uth[(size_t)o * RANKc + r] = h;
            g_utl[(size_t)o * RANKc + r] = l;
        }
    } else {
        const int b = blockIdx.x - 2560;             // 0..1183
        const float thr = threshold[0];
        float mpre = 0.f, mdec = 0.f;
        const size_t n4 = (size_t)MTOK * Dc / 4;
        for (size_t i4 = (size_t)b * blockDim.x + threadIdx.x; i4 < n4;
             i4 += (size_t)1184 * blockDim.x) {
            size_t i = i4 * 4;
            int d = (int)(i & (Dc - 1));
            int t = (int)((i >> 12) & (Tc - 1));
            float4 v = *reinterpret_cast<const float4*>(x + i);
            if (t < SPARSE_T) {
                mpre = fmaxf(mpre, fmaxf(fmaxf(fabsf(v.x), fabsf(v.y)), fmaxf(fabsf(v.z), fabsf(v.w))));
            } else {
                float4 sv = *reinterpret_cast<const float4*>(scale_vec + d);
                if (fabsf(v.x * sv.x) > thr) mdec = fmaxf(mdec, fabsf(v.x));
                if (fabsf(v.y * sv.y) > thr) mdec = fmaxf(mdec, fabsf(v.y));
                if (fabsf(v.z * sv.z) > thr) mdec = fmaxf(mdec, fabsf(v.z));
                if (fabsf(v.w * sv.w) > thr) mdec = fmaxf(mdec, fabsf(v.w));
            }
        }
#pragma unroll
        for (int o = 16; o; o >>= 1) {
            mpre = fmaxf(mpre, __shfl_xor_sync(0xffffffffu, mpre, o));
            mdec = fmaxf(mdec, __shfl_xor_sync(0xffffffffu, mdec, o));
        }
        __shared__ float spre[8], sdec[8];
        int w = threadIdx.x >> 5;
        if ((threadIdx.x & 31) == 0) { spre[w] = mpre; sdec[w] = mdec; }
        __syncthreads();
        if (threadIdx.x == 0) {
            float a = spre[0], bb = sdec[0];
            for (int i = 1; i < 8; i++) { a = fmaxf(a, spre[i]); bb = fmaxf(bb, sdec[i]); }
            atomicMax(&g_maxbits[0], __float_as_uint(a));
            atomicMax(&g_maxbits[1], __float_as_uint(bb));
        }
    }
}

DEV_INLINE float fp4_mag(float a) {
    return a > 2.5f ? (a > 3.5f ? (a > 5.0f ? 6.0f : 4.0f) : 3.0f)
                    : (a > 1.25f ? (a > 1.75f ? 2.0f : 1.5f)
                                 : (a > 0.75f ? 1.0f : (a > 0.25f ? 0.5f : 0.0f)));
}

// One block per token. LR fp16-only; prefill rows skip the LR store entirely.
__global__ void __launch_bounds__(256, 5) quantize_kernel(const float* __restrict__ x,
                                                          const float* __restrict__ scale_vec,
                                                          const float* __restrict__ threshold,
                                                          const int* __restrict__ rix) {
    __shared__ float sx[Dc];   // 16 KB

    const int tok = blockIdx.x;
    const int t = tok & (Tc - 1);
    const bool decode = (t >= SPARSE_T);
    const float thr = threshold[0];
    const float s = fmaxf(__uint_as_float(g_maxbits[decode ? 1 : 0]) / SCALE_CAP, 1e-12f);
    const float inv_s = 1.0f / s;
    const float* xrow = x + (size_t)tok * Dc;
    const int tid = threadIdx.x;

    __half* lrh = g_LRh + (size_t)tok * Dc;

    // phase 1: masked value -> sx; LR (fp16) -> global (decode rows only)
#pragma unroll
    for (int it = 0; it < 4; it++) {
        int i = it * 1024 + tid * 4;
        float4 v = *reinterpret_cast<const float4*>(xrow + i);
        if (decode) {
            float4 sv = *reinterpret_cast<const float4*>(scale_vec + i);
            bool m0 = fabsf(v.x * sv.x) > thr, m1 = fabsf(v.y * sv.y) > thr;
            bool m2 = fabsf(v.z * sv.z) > thr, m3 = fabsf(v.w * sv.w) > thr;
            float4 masked = make_float4(m0 ? v.x : 0.f, m1 ? v.y : 0.f, m2 ? v.z : 0.f, m3 ? v.w : 0.f);
            float4 lr     = make_float4(m0 ? 0.f : v.x, m1 ? 0.f : v.y, m2 ? 0.f : v.z, m3 ? 0.f : v.w);
            *reinterpret_cast<float4*>(sx + i) = masked;
            __half2 h01 = __floats2half2_rn(lr.x, lr.y);
            __half2 h23 = __floats2half2_rn(lr.z, lr.w);
            uint2 uh;
            uh.x = *reinterpret_cast<unsigned*>(&h01);
            uh.y = *reinterpret_cast<unsigned*>(&h23);
            *reinterpret_cast<uint2*>(lrh + i) = uh;
        } else {
            *reinterpret_cast<float4*>(sx + i) = v;
        }
    }
    __syncthreads();

    // phase 2: fp4 quant in reordered space; indices straight from global.
    {
        int j0 = (tid < 8) ? tid * 16 : SELECTc + (tid - 8) * GROUPc;
        int ris[16];
#pragma unroll
        for (int c = 0; c < 4; c++)
            *reinterpret_cast<int4*>(ris + c * 4) =
                *reinterpret_cast<const int4*>(rix + j0 + c * 4);

        if (tid < 8) {
#pragma unroll
            for (int k = 0; k < 16; k++) {
                int ri = ris[k];
                float xr = sx[ri] * inv_s;
                sx[ri] = xr * s;
            }
        } else {
            float gmax = 0.f;
#pragma unroll
            for (int k = 0; k < GROUPc; k++) {
                float v = sx[ris[k]] * inv_s;
                gmax = fmaxf(gmax, fabsf(v));
            }
            float gs, inv_gs;
            if (gmax > 0.f) { gs = gmax / 6.0f; inv_gs = 6.0f / gmax; }
            else            { gs = 1.0f;       inv_gs = 1.0f; }
#pragma unroll
            for (int k = 0; k < GROUPc; k++) {
                int ri = ris[k];
                float v = sx[ri] * inv_s;
                float r = v * inv_gs;
                float q = fp4_mag(fabsf(r));
                q = (r < 0.f) ? -q : q;
                sx[ri] = (q * gs) * s;
            }
        }
    }
    __syncthreads();

    // phase 3: split-fp16 writeback (packed conversions)
    __half* xh = g_Xh + (size_t)tok * Dc;
    __half* xl = g_Xl + (size_t)tok * Dc;
#pragma unroll
    for (int it = 0; it < 4; it++) {
        int i = it * 1024 + tid * 4;
        float4 v = *reinterpret_cast<const float4*>(sx + i);
        uint2 uh, ul;
        split4(v, uh, ul);
        *reinterpret_cast<uint2*>(xh + i) = uh;
        *reinterpret_cast<uint2*>(xl + i) = ul;
    }
}

__global__ void sum_split_kernel() {
    int i = blockIdx.x * blockDim.x + threadIdx.x;
    if (i < MTOK * RANKc) {
        float s = g_tmp4[0][i] + g_tmp4[1][i] + g_tmp4[2][i] + g_tmp4[3][i];
        __half h, l; split2(s, h, l);
        g_tmph[i] = h; g_tmpl[i] = l;
    }
}

// ---------------- PTX helpers ----------------
DEV_INLINE unsigned smem_u32(const void* p) { return (unsigned)__cvta_generic_to_shared(p); }

DEV_INLINE void cp_async16(unsigned dst, const void* src) {
    asm volatile("cp.async.cg.shared.global [%0], [%1], 16;\n" :: "r"(dst), "l"(src));
}
DEV_INLINE void cp_commit() { asm volatile("cp.async.commit_group;\n"); }
template <int N> DEV_INLINE void cp_wait() { asm volatile("cp.async.wait_group %0;\n" :: "n"(N)); }

DEV_INLINE void ldmatrix_x4(unsigned& r0, unsigned& r1, unsigned& r2, unsigned& r3, unsigned addr) {
    asm volatile("ldmatrix.sync.aligned.m8n8.x4.shared.b16 {%0,%1,%2,%3}, [%4];\n"
                 : "=r"(r0), "=r"(r1), "=r"(r2), "=r"(r3) : "r"(addr));
}
DEV_INLINE void mma16816(float& d0, float& d1, float& d2, float& d3,
                         unsigned a0, unsigned a1, unsigned a2, unsigned a3,
                         unsigned b0, unsigned b1) {
    asm volatile("mma.sync.aligned.m16n8k16.row.col.f32.f16.f16.f32 "
                 "{%0,%1,%2,%3}, {%4,%5,%6,%7}, {%8,%9}, {%0,%1,%2,%3};\n"
                 : "+f"(d0), "+f"(d1), "+f"(d2), "+f"(d3)
                 : "r"(a0), "r"(a1), "r"(a2), "r"(a3), "r"(b0), "r"(b1));
}

// ================= fused main GEMM (R8-proven config, unchanged) =================
constexpr int MAIN_KT = KFUSE / 32;           // 132
constexpr int MAIN_SMEM = 3 * 2048 * 16;      // 96 KB

__global__ void __launch_bounds__(256, 2)
gemm_main_kernel(const __half* __restrict__ Ah, const __half* __restrict__ Al,
                 const __half* __restrict__ Bh, const __half* __restrict__ Bl,
                 const __half* __restrict__ Eah, const __half* __restrict__ Eal,
                 const __half* __restrict__ Ebh, const __half* __restrict__ Ebl,
                 float* __restrict__ C, const float* __restrict__ bias) {
    extern __shared__ uint4 S[];
    const int tid = threadIdx.x;

    // supertile raster: groups of 32 M-tiles x 8 N-tiles
    const int bid = blockIdx.x;
    const int gid = bid >> 8, wit = bid & 255;
    const int mt = (gid & 1) * 32 + (wit & 31);
    const int nt = (gid >> 1) * 8 + (wit >> 5);
    const int rowA0 = mt * 128;
    const int rowB0 = nt * 128;

    auto load_tile = [&](int stage, int kt) {
        const int so = stage * 2048;
#pragma unroll
        for (int i = tid; i < 512; i += 256) {
            int r = i >> 2, c = i & 3;
            int d = so + (r << 2) + (c ^ ((r >> 1) & 3));
            if (kt < Dc / 32) {
                size_t srcA = (size_t)(rowA0 + r) * Dc + kt * 32 + c * 8;
                cp_async16(smem_u32(&S[d]), Ah + srcA);
                cp_async16(smem_u32(&S[d + 512]), Al + srcA);
                size_t srcB = (size_t)(rowB0 + r) * Dc + kt * 32 + c * 8;
                cp_async16(smem_u32(&S[d + 1024]), Bh + srcB);
                cp_async16(smem_u32(&S[d + 1536]), Bl + srcB);
            } else {
                int k0 = (kt - Dc / 32) * 32;
                size_t srcA = (size_t)(rowA0 + r) * RANKc + k0 + c * 8;
                cp_async16(smem_u32(&S[d]), Eah + srcA);
                cp_async16(smem_u32(&S[d + 512]), Eal + srcA);
                size_t srcB = (size_t)(rowB0 + r) * RANKc + k0 + c * 8;
                cp_async16(smem_u32(&S[d + 1024]), Ebh + srcB);
                cp_async16(smem_u32(&S[d + 1536]), Ebl + srcB);
            }
        }
        cp_commit();
    };

    const int warp = tid >> 5, lane = tid & 31;
    const int wm = warp & 1;    // 2 warp-rows of 64
    const int wn = warp >> 1;   // 4 warp-cols of 32

    float acc[4][4][4];
#pragma unroll
    for (int i = 0; i < 4; i++)
#pragma unroll
        for (int j = 0; j < 4; j++)
#pragma unroll
            for (int k = 0; k < 4; k++) acc[i][j][k] = 0.f;

    load_tile(0, 0);
    load_tile(1, 1);

    int cstage = 0;
    for (int kt = 0; kt < MAIN_KT; kt++) {
        if (kt >= MAIN_KT - 1) cp_wait<0>(); else cp_wait<1>();
        __syncthreads();
        if (kt + 2 < MAIN_KT) {
            int lstage = cstage == 0 ? 2 : cstage - 1;
            load_tile(lstage, kt + 2);
        }
        const int so = cstage * 2048;
#pragma unroll
        for (int ks = 0; ks < 2; ks++) {
            unsigned bh[4][2], bl[4][2];
#pragma unroll
            for (int nb = 0; nb < 2; nb++) {
                int n = wn * 32 + nb * 16 + (lane & 7) + ((lane >> 4) << 3);
                int kc = ks * 2 + ((lane >> 3) & 1);
                int idx = so + 1024 + (n << 2) + (kc ^ ((n >> 1) & 3));
                unsigned r0, r1, r2, r3;
                ldmatrix_x4(r0, r1, r2, r3, smem_u32(&S[idx]));
                bh[nb * 2][0] = r0;     bh[nb * 2][1] = r1;
                bh[nb * 2 + 1][0] = r2; bh[nb * 2 + 1][1] = r3;
                ldmatrix_x4(r0, r1, r2, r3, smem_u32(&S[idx + 512]));
                bl[nb * 2][0] = r0;     bl[nb * 2][1] = r1;
                bl[nb * 2 + 1][0] = r2; bl[nb * 2 + 1][1] = r3;
            }
#pragma unroll
            for (int mp = 0; mp < 2; mp++) {
                unsigned ah[2][4], al[2][4];
#pragma unroll
                for (int m2 = 0; m2 < 2; m2++) {
                    int mi = mp * 2 + m2;
                    int m = wm * 64 + mi * 16 + (lane & 15);
                    int kc = ks * 2 + (lane >> 4);
                    int idx = so + (m << 2) + (kc ^ ((m >> 1) & 3));
                    ldmatrix_x4(ah[m2][0], ah[m2][1], ah[m2][2], ah[m2][3], smem_u32(&S[idx]));
                    ldmatrix_x4(al[m2][0], al[m2][1], al[m2][2], al[m2][3], smem_u32(&S[idx + 512]));
                }
#pragma unroll
                for (int m2 = 0; m2 < 2; m2++)
#pragma unroll
                    for (int ni = 0; ni < 4; ni++) {
                        float* d = acc[mp * 2 + m2][ni];
                        mma16816(d[0], d[1], d[2], d[3],
                                 ah[m2][0], ah[m2][1], ah[m2][2], ah[m2][3], bh[ni][0], bh[ni][1]);
                        mma16816(d[0], d[1], d[2], d[3],
                                 al[m2][0], al[m2][1], al[m2][2], al[m2][3], bh[ni][0], bh[ni][1]);
                        mma16816(d[0], d[1], d[2], d[3],
                                 ah[m2][0], ah[m2][1], ah[m2][2], ah[m2][3], bl[ni][0], bl[ni][1]);
                    }
            }
        }
        cstage = (cstage == 2) ? 0 : cstage + 1;
    }

    const int crow0 = rowA0 + wm * 64;
    const int ccol0 = rowB0 + wn * 32;
#pragma unroll
    for (int mi = 0; mi < 4; mi++) {
#pragma unroll
        for (int ni = 0; ni < 4; ni++) {
            int r = crow0 + mi * 16 + (lane >> 2);
            int c = ccol0 + ni * 8 + (lane & 3) * 2;
            float b0 = bias[c], b1 = bias[c + 1];
            float* d = acc[mi][ni];
            *reinterpret_cast<float2*>(C + (size_t)r * OUTc + c) =
                make_float2(d[0] + b0, d[1] + b1);
            *reinterpret_cast<float2*>(C + (size_t)(r + 8) * OUTc + c) =
                make_float2(d[2] + b0, d[3] + b1);
        }
    }
}

// ---------------- LR@vs with 4-way K-split: A fp16-only, B split (2 MMA terms) ----------------
__global__ void __launch_bounds__(256, 2)
gemm_lr1_kernel(const __half* __restrict__ A,
                const __half* __restrict__ Bh, const __half* __restrict__ Bl) {
    constexpr int BK = 32;
    constexpr int KT = 32;               // 1024 / 32
    extern __shared__ uint4 Sd[];
    const int tid = threadIdx.x;
    const int rowA0 = blockIdx.y * 128;
    const int kz = blockIdx.z;
    const int kbase = kz * (Dc / 4);
    float* out = g_tmp4[kz];

    auto load_tile = [&](int stage, int kt) {
        const int k0 = kbase + kt * BK;
        const int so = stage * 1536;
#pragma unroll
        for (int i = tid; i < 512; i += 256) {
            int r = i >> 2, c = i & 3;
            int d = so + (r << 2) + (c ^ ((r >> 1) & 3));
            size_t srcA = (size_t)(rowA0 + r) * Dc + k0 + c * 8;
            cp_async16(smem_u32(&Sd[d]), A + srcA);
            size_t srcB = (size_t)r * Dc + k0 + c * 8;   // rowB0 = 0
            cp_async16(smem_u32(&Sd[d + 512]), Bh + srcB);
            cp_async16(smem_u32(&Sd[d + 1024]), Bl + srcB);
        }
        cp_commit();
    };

    const int warp = tid >> 5, lane = tid & 31;
    const int wm = warp & 1;
    const int wn = warp >> 1;

    float acc[4][4][4];
#pragma unroll
    for (int i = 0; i < 4; i++)
#pragma unroll
        for (int j = 0; j < 4; j++)
#pragma unroll
            for (int k = 0; k < 4; k++) acc[i][j][k] = 0.f;

    load_tile(0, 0);
    load_tile(1, 1);

    int cstage = 0;
    for (int kt = 0; kt < KT; kt++) {
        if (kt >= KT - 1) cp_wait<0>(); else cp_wait<1>();
        __syncthreads();
        if (kt + 2 < KT) {
            int lstage = cstage == 0 ? 2 : cstage - 1;
            load_tile(lstage, kt + 2);
        }
        const int so = cstage * 1536;
#pragma unroll
        for (int ks = 0; ks < 2; ks++) {
            unsigned bh[4][2], bl[4][2];
#pragma unroll
            for (int nb = 0; nb < 2; nb++) {
                int n = wn * 32 + nb * 16 + (lane & 7) + ((lane >> 4) << 3);
                int kc = ks * 2 + ((lane >> 3) & 1);
                int idx = so + 512 + (n << 2) + (kc ^ ((n >> 1) & 3));
                unsigned r0, r1, r2, r3;
                ldmatrix_x4(r0, r1, r2, r3, smem_u32(&Sd[idx]));
                bh[nb * 2][0] = r0;     bh[nb * 2][1] = r1;
                bh[nb * 2 + 1][0] = r2; bh[nb * 2 + 1][1] = r3;
                ldmatrix_x4(r0, r1, r2, r3, smem_u32(&Sd[idx + 512]));
                bl[nb * 2][0] = r0;     bl[nb * 2][1] = r1;
                bl[nb * 2 + 1][0] = r2; bl[nb * 2 + 1][1] = r3;
            }
#pragma unroll
            for (int mp = 0; mp < 2; mp++) {
                unsigned a[2][4];
#pragma unroll
                for (int m2 = 0; m2 < 2; m2++) {
                    int mi = mp * 2 + m2;
                    int m = wm * 64 + mi * 16 + (lane & 15);
                    int kc = ks * 2 + (lane >> 4);
                    int idx = so + (m << 2) + (kc ^ ((m >> 1) & 3));
                    ldmatrix_x4(a[m2][0], a[m2][1], a[m2][2], a[m2][3], smem_u32(&Sd[idx]));
                }
#pragma unroll
                for (int m2 = 0; m2 < 2; m2++)
#pragma unroll
                    for (int ni = 0; ni < 4; ni++) {
                        float* d = acc[mp * 2 + m2][ni];
                        mma16816(d[0], d[1], d[2], d[3],
                                 a[m2][0], a[m2][1], a[m2][2], a[m2][3], bh[ni][0], bh[ni][1]);
                        mma16816(d[0], d[1], d[2], d[3],
                                 a[m2][0], a[m2][1], a[m2][2], a[m2][3], bl[ni][0], bl[ni][1]);
                    }
            }
        }
        cstage = (cstage == 2) ? 0 : cstage + 1;
    }

    const int crow0 = rowA0 + wm * 64;
    const int ccol0 = wn * 32;
#pragma unroll
    for (int mi = 0; mi < 4; mi++) {
#pragma unroll
        for (int ni = 0; ni < 4; ni++) {
            int r = crow0 + mi * 16 + (lane >> 2);
            int c = ccol0 + ni * 8 + (lane & 3) * 2;
            float* d = acc[mi][ni];
            *reinterpret_cast<float2*>(out + (size_t)r * RANKc + c) = make_float2(d[0], d[1]);
            *reinterpret_cast<float2*>(out + (size_t)(r + 8) * RANKc + c) = make_float2(d[2], d[3]);
        }
    }
}

// ---------------- launch ----------------
extern "C" void kernel_launch(void* const* d_in, const int* in_sizes, int n_in,
                              void* d_out, int out_size) {
    const float* x         = (const float*)d_in[0];
    const float* W         = (const float*)d_in[1];
    const float* bias      = (const float*)d_in[2];
    const float* vs        = (const float*)d_in[3];
    const float* u_t       = (const float*)d_in[4];
    const float* scale_vec = (const float*)d_in[5];
    const float* threshold = (const float*)d_in[6];
    const int*   rix       = (const int*)d_in[7];

    void *pXh, *pXl, *pLRh, *pWhh, *pWll, *pvsh, *pvsl, *puth, *putl, *ptmph, *ptmpl, *pmax;
    cudaGetSymbolAddress(&pXh,  g_Xh);
    cudaGetSymbolAddress(&pXl,  g_Xl);
    cudaGetSymbolAddress(&pLRh, g_LRh);
    cudaGetSymbolAddress(&pWhh, g_Whh);
    cudaGetSymbolAddress(&pWll, g_Wll);
    cudaGetSymbolAddress(&pvsh, g_vsh);
    cudaGetSymbolAddress(&pvsl, g_vsl);
    cudaGetSymbolAddress(&puth, g_uth);
    cudaGetSymbolAddress(&putl, g_utl);
    cudaGetSymbolAddress(&ptmph, g_tmph);
    cudaGetSymbolAddress(&ptmpl, g_tmpl);
    cudaGetSymbolAddress(&pmax, g_maxbits);

    constexpr int SMEM_LR1 = 3 * 1536 * 16; // 72 KB
    cudaFuncSetAttribute(gemm_lr1_kernel, cudaFuncAttributeMaxDynamicSharedMemorySize, SMEM_LR1);
    cudaFuncSetAttribute(gemm_main_kernel, cudaFuncAttributeMaxDynamicSharedMemorySize, MAIN_SMEM);

    // [0] reset absmax accumulators (graph memset node)
    cudaMemsetAsync(pmax, 0, 2 * sizeof(unsigned));
    // [1] merged prep: W/vs/u_t conversion overlapped with x absmax reduction
    prep_kernel<<<3744, 256>>>(W, vs, u_t, x, scale_vec, threshold);
    // [2] activation fp4-quant + fp16 split (packed conversions)
    quantize_kernel<<<MTOK, 256>>>(x, scale_vec, threshold, rix);
    // [3] tmp partials: LR @ vs, 4-way K-split (2-term exact-product)
    {
        dim3 grid(1, MTOK / 128, 4);
        gemm_lr1_kernel<<<grid, 256, SMEM_LR1>>>(
            (const __half*)pLRh,
            (const __half*)pvsh, (const __half*)pvsl);
    }
    // [4] reduce partials -> split-fp16 tmp
    sum_split_kernel<<<(MTOK * RANKc + 255) / 256, 256>>>();
    // [5] fused MAIN: out = Xq @ W^T + tmp @ u_t + bias  (K=4224, R8 config)
    gemm_main_kernel<<<2048, 256, MAIN_SMEM>>>(
        (const __half*)pXh, (const __half*)pXl,
        (const __half*)pWhh, (const __half*)pWll,
        (const __half*)ptmph, (const __half*)ptmpl,
        (const __half*)puth, (const __half*)putl,
        (float*)d_out, bias);
}